// round 1
// baseline (speedup 1.0000x reference)
#include <cuda_runtime.h>
#include <math.h>

#define NN  84
#define PP  3486
#define HH  2048
#define H2  1024
#define G3  (3*HH)          // 6144
#define LN_EPS 1e-5f
#define RED_BLOCKS 1024

// ---------------- scratch (device globals; no runtime allocation) -----------
__device__ float  g_gi[(size_t)NN * G3];        // node-level GRU input gates
__device__ float  g_gh[(size_t)PP * G3];        // hidden gate pre-activations
__device__ float  g_h1[(size_t)PP * HH];
__device__ float  g_h2[(size_t)PP * HH];
__device__ float  g_a [(size_t)PP * HH];
__device__ float  g_b [(size_t)PP * HH];
__device__ float  g_c [(size_t)PP * H2];
__device__ float  g_d [(size_t)PP * H2];
__device__ float  g_vals[PP];
__device__ int    g_iu[PP];
__device__ int    g_ju[PP];
__device__ double g_part[2 * RED_BLOCKS];
__device__ float  g_stats[2];                   // mu, rsigma

// ---------------- pair index generation -------------------------------------
__global__ void make_pairs_kernel(int* __restrict__ iu, int* __restrict__ ju) {
    int p = blockIdx.x * blockDim.x + threadIdx.x;
    if (p >= PP) return;
    int off = 0;
    for (int i = 0; i < NN - 1; i++) {
        int cnt = NN - 1 - i;
        if (p < off + cnt) { iu[p] = i; ju[p] = i + 1 + (p - off); return; }
        off += cnt;
    }
}

// ---------------- SGEMM: C[M,Nc] = A[M,K] @ W[Nc,K]^T + bias, opt ReLU ------
// 128x128 tile, BK=16, 256 threads, 8x8 per thread.
template<int RELU>
__global__ __launch_bounds__(256, 2)
void sgemm_nt(const float* __restrict__ A, const float* __restrict__ W,
              const float* __restrict__ bias, float* __restrict__ C,
              int M, int Nc, int K)
{
    __shared__ float As[16][128];
    __shared__ float Bs[16][128];

    const int tid  = threadIdx.x;
    const int bm   = blockIdx.y * 128;
    const int bn   = blockIdx.x * 128;
    const int lrow = tid >> 1;           // 0..127
    const int lk   = (tid & 1) << 3;     // 0 or 8
    const int rm   = (tid >> 4) << 3;    // 0..120
    const int rn   = (tid & 15) << 3;    // 0..120

    float acc[8][8];
    #pragma unroll
    for (int i = 0; i < 8; i++)
        #pragma unroll
        for (int j = 0; j < 8; j++) acc[i][j] = 0.f;

    const bool arow_ok = (bm + lrow) < M;
    const float* Ap = A + (size_t)(bm + lrow) * K + lk;
    const float* Wp = W + (size_t)(bn + lrow) * K + lk;

    for (int k0 = 0; k0 < K; k0 += 16) {
        float4 a0 = make_float4(0.f,0.f,0.f,0.f), a1 = a0;
        if (arow_ok) {
            a0 = *(const float4*)(Ap + k0);
            a1 = *(const float4*)(Ap + k0 + 4);
        }
        float4 b0 = *(const float4*)(Wp + k0);
        float4 b1 = *(const float4*)(Wp + k0 + 4);

        __syncthreads();
        As[lk+0][lrow] = a0.x; As[lk+1][lrow] = a0.y;
        As[lk+2][lrow] = a0.z; As[lk+3][lrow] = a0.w;
        As[lk+4][lrow] = a1.x; As[lk+5][lrow] = a1.y;
        As[lk+6][lrow] = a1.z; As[lk+7][lrow] = a1.w;
        Bs[lk+0][lrow] = b0.x; Bs[lk+1][lrow] = b0.y;
        Bs[lk+2][lrow] = b0.z; Bs[lk+3][lrow] = b0.w;
        Bs[lk+4][lrow] = b1.x; Bs[lk+5][lrow] = b1.y;
        Bs[lk+6][lrow] = b1.z; Bs[lk+7][lrow] = b1.w;
        __syncthreads();

        #pragma unroll
        for (int kk = 0; kk < 16; kk++) {
            float4 av0 = *(const float4*)&As[kk][rm];
            float4 av1 = *(const float4*)&As[kk][rm + 4];
            float4 bv0 = *(const float4*)&Bs[kk][rn];
            float4 bv1 = *(const float4*)&Bs[kk][rn + 4];
            float a[8] = {av0.x, av0.y, av0.z, av0.w, av1.x, av1.y, av1.z, av1.w};
            float b[8] = {bv0.x, bv0.y, bv0.z, bv0.w, bv1.x, bv1.y, bv1.z, bv1.w};
            #pragma unroll
            for (int i = 0; i < 8; i++)
                #pragma unroll
                for (int j = 0; j < 8; j++)
                    acc[i][j] = fmaf(a[i], b[j], acc[i][j]);
        }
    }

    #pragma unroll
    for (int i = 0; i < 8; i++) {
        int row = bm + rm + i;
        if (row >= M) continue;
        float* Cp = C + (size_t)row * Nc + bn + rn;
        float4 o0, o1;
        float v;
        v = acc[i][0] + bias[bn+rn+0]; if (RELU) v = fmaxf(v, 0.f); o0.x = v;
        v = acc[i][1] + bias[bn+rn+1]; if (RELU) v = fmaxf(v, 0.f); o0.y = v;
        v = acc[i][2] + bias[bn+rn+2]; if (RELU) v = fmaxf(v, 0.f); o0.z = v;
        v = acc[i][3] + bias[bn+rn+3]; if (RELU) v = fmaxf(v, 0.f); o0.w = v;
        v = acc[i][4] + bias[bn+rn+4]; if (RELU) v = fmaxf(v, 0.f); o1.x = v;
        v = acc[i][5] + bias[bn+rn+5]; if (RELU) v = fmaxf(v, 0.f); o1.y = v;
        v = acc[i][6] + bias[bn+rn+6]; if (RELU) v = fmaxf(v, 0.f); o1.z = v;
        v = acc[i][7] + bias[bn+rn+7]; if (RELU) v = fmaxf(v, 0.f); o1.w = v;
        *(float4*)(Cp)     = o0;
        *(float4*)(Cp + 4) = o1;
    }
}

// ---------------- GRU gate combine ------------------------------------------
__device__ __forceinline__ float sigmoidf_(float x) {
    return 1.f / (1.f + expf(-x));
}

__global__ void gru_combine_kernel(const float* __restrict__ gh,
                                   const float* __restrict__ gi,
                                   const int*   __restrict__ node_idx,
                                   const float* __restrict__ hprev,
                                   float*       __restrict__ hout)
{
    size_t idx = (size_t)blockIdx.x * blockDim.x + threadIdx.x;
    if (idx >= (size_t)PP * HH) return;
    int p = (int)(idx >> 11);        // /2048
    int j = (int)(idx & 2047);
    int q = node_idx[p];
    const float* gip = gi + (size_t)q * G3;
    const float* ghp = gh + (size_t)p * G3;
    float r = sigmoidf_(gip[j]        + ghp[j]);
    float z = sigmoidf_(gip[j + HH]   + ghp[j + HH]);
    float n = tanhf    (gip[j + 2*HH] + r * ghp[j + 2*HH]);
    float h = hprev[idx];
    hout[idx] = (1.f - z) * n + z * h;
}

// ---------------- full-tensor LayerNorm (two-stage deterministic reduce) ----
__global__ void ln_reduce1(const float* __restrict__ x, size_t n,
                           double* __restrict__ part)
{
    double s = 0.0, ss = 0.0;
    size_t stride = (size_t)gridDim.x * blockDim.x;
    for (size_t i = (size_t)blockIdx.x * blockDim.x + threadIdx.x; i < n; i += stride) {
        double v = (double)x[i];
        s += v; ss += v * v;
    }
    __shared__ double sh[256], sh2[256];
    sh[threadIdx.x] = s; sh2[threadIdx.x] = ss;
    __syncthreads();
    for (int o = 128; o > 0; o >>= 1) {
        if (threadIdx.x < o) {
            sh[threadIdx.x]  += sh[threadIdx.x + o];
            sh2[threadIdx.x] += sh2[threadIdx.x + o];
        }
        __syncthreads();
    }
    if (threadIdx.x == 0) {
        part[blockIdx.x]              = sh[0];
        part[RED_BLOCKS + blockIdx.x] = sh2[0];
    }
}

__global__ void ln_reduce2(const double* __restrict__ part,
                           unsigned long long n, float* __restrict__ stats)
{
    __shared__ double sh[256], sh2[256];
    double s = 0.0, ss = 0.0;
    for (int i = threadIdx.x; i < RED_BLOCKS; i += 256) {
        s  += part[i];
        ss += part[RED_BLOCKS + i];
    }
    sh[threadIdx.x] = s; sh2[threadIdx.x] = ss;
    __syncthreads();
    for (int o = 128; o > 0; o >>= 1) {
        if (threadIdx.x < o) {
            sh[threadIdx.x]  += sh[threadIdx.x + o];
            sh2[threadIdx.x] += sh2[threadIdx.x + o];
        }
        __syncthreads();
    }
    if (threadIdx.x == 0) {
        double inv = 1.0 / (double)n;
        double mu  = sh[0] * inv;
        double var = sh2[0] * inv - mu * mu;
        stats[0] = (float)mu;
        stats[1] = (float)(1.0 / sqrt(var + (double)LN_EPS));
    }
}

__global__ void ln_apply(const float* __restrict__ x, const float* __restrict__ w,
                         const float* __restrict__ b, const float* __restrict__ stats,
                         float* __restrict__ y, size_t n)
{
    size_t i = (size_t)blockIdx.x * blockDim.x + threadIdx.x;
    if (i >= n) return;
    float mu = stats[0], rs = stats[1];
    y[i] = (x[i] - mu) * rs * w[i] + b[i];
}

// ---------------- final row-dot + sigmoid ------------------------------------
__global__ void final_dot_kernel(const float* __restrict__ h,
                                 const float* __restrict__ W4,
                                 const float* __restrict__ b4,
                                 float* __restrict__ vals)
{
    int p = blockIdx.x * 8 + (threadIdx.x >> 5);
    int lane = threadIdx.x & 31;
    if (p >= PP) return;
    const float4* hp = (const float4*)(h + (size_t)p * H2);
    const float4* wp = (const float4*)W4;
    float s = 0.f;
    #pragma unroll
    for (int i = lane; i < H2 / 4; i += 32) {
        float4 a = hp[i], w = wp[i];
        s += a.x*w.x + a.y*w.y + a.z*w.z + a.w*w.w;
    }
    #pragma unroll
    for (int o = 16; o > 0; o >>= 1) s += __shfl_xor_sync(0xffffffffu, s, o);
    if (lane == 0) {
        vals[p] = 1.f / (1.f + expf(-(s + b4[0])));
    }
}

// ---------------- output assembly --------------------------------------------
__global__ void zero_out_kernel(float* __restrict__ out) {
    int i = blockIdx.x * blockDim.x + threadIdx.x;
    if (i < NN * NN) out[i] = 0.f;
}

__global__ void scatter_kernel(const float* __restrict__ vals,
                               const int* __restrict__ iu, const int* __restrict__ ju,
                               float* __restrict__ out)
{
    int p = blockIdx.x * blockDim.x + threadIdx.x;
    if (p >= PP) return;
    float v = vals[p];
    int i = iu[p], j = ju[p];
    out[i * NN + j] = v;
    out[j * NN + i] = v;
}

// ---------------- driver ------------------------------------------------------
extern "C" void kernel_launch(void* const* d_in, const int* in_sizes, int n_in,
                              void* d_out, int out_size)
{
    const float* x    = (const float*)d_in[0];
    const float* hid  = (const float*)d_in[1];
    const float* Wih  = (const float*)d_in[2];
    const float* Whh  = (const float*)d_in[3];
    const float* bih  = (const float*)d_in[4];
    const float* bhh  = (const float*)d_in[5];
    const float* W1   = (const float*)d_in[6];
    const float* b1   = (const float*)d_in[7];
    const float* ln1w = (const float*)d_in[8];
    const float* ln1b = (const float*)d_in[9];
    const float* W2   = (const float*)d_in[10];
    const float* b2   = (const float*)d_in[11];
    const float* ln2w = (const float*)d_in[12];
    const float* ln2b = (const float*)d_in[13];
    const float* W3   = (const float*)d_in[14];
    const float* b3   = (const float*)d_in[15];
    const float* ln3w = (const float*)d_in[16];
    const float* ln3b = (const float*)d_in[17];
    const float* W4   = (const float*)d_in[18];
    const float* b4   = (const float*)d_in[19];
    float* out = (float*)d_out;

    float *gi, *gh, *h1, *h2, *a, *b, *c, *d, *vals, *stats;
    int *iu, *ju;
    double* part;
    cudaGetSymbolAddress((void**)&gi,    g_gi);
    cudaGetSymbolAddress((void**)&gh,    g_gh);
    cudaGetSymbolAddress((void**)&h1,    g_h1);
    cudaGetSymbolAddress((void**)&h2,    g_h2);
    cudaGetSymbolAddress((void**)&a,     g_a);
    cudaGetSymbolAddress((void**)&b,     g_b);
    cudaGetSymbolAddress((void**)&c,     g_c);
    cudaGetSymbolAddress((void**)&d,     g_d);
    cudaGetSymbolAddress((void**)&vals,  g_vals);
    cudaGetSymbolAddress((void**)&iu,    g_iu);
    cudaGetSymbolAddress((void**)&ju,    g_ju);
    cudaGetSymbolAddress((void**)&part,  g_part);
    cudaGetSymbolAddress((void**)&stats, g_stats);

    const size_t nPH  = (size_t)PP * HH;   // 7,139,328
    const size_t nPH2 = (size_t)PP * H2;   // 3,569,664

    // pair indices
    make_pairs_kernel<<<(PP + 255) / 256, 256>>>(iu, ju);

    // gi for all 84 nodes: [84, 6144] = x[84,64] @ Wih^T + bih
    {
        dim3 grid(G3 / 128, (NN + 127) / 128);
        sgemm_nt<0><<<grid, 256>>>(x, Wih, bih, gi, NN, G3, 64);
    }

    // GRU step 1: gh = hid @ Whh^T + bhh ; combine with gi[iu]
    {
        dim3 grid(G3 / 128, (PP + 127) / 128);
        sgemm_nt<0><<<grid, 256>>>(hid, Whh, bhh, gh, PP, G3, HH);
    }
    gru_combine_kernel<<<(unsigned)((nPH + 255) / 256), 256>>>(gh, gi, iu, hid, h1);

    // GRU step 2
    {
        dim3 grid(G3 / 128, (PP + 127) / 128);
        sgemm_nt<0><<<grid, 256>>>(h1, Whh, bhh, gh, PP, G3, HH);
    }
    gru_combine_kernel<<<(unsigned)((nPH + 255) / 256), 256>>>(gh, gi, ju, h1, h2);

    // L1 + ReLU -> full LN
    {
        dim3 grid(HH / 128, (PP + 127) / 128);
        sgemm_nt<1><<<grid, 256>>>(h2, W1, b1, a, PP, HH, HH);
    }
    ln_reduce1<<<RED_BLOCKS, 256>>>(a, nPH, part);
    ln_reduce2<<<1, 256>>>(part, (unsigned long long)nPH, stats);
    ln_apply<<<(unsigned)((nPH + 255) / 256), 256>>>(a, ln1w, ln1b, stats, b, nPH);

    // L2 + ReLU -> full LN
    {
        dim3 grid(H2 / 128, (PP + 127) / 128);
        sgemm_nt<1><<<grid, 256>>>(b, W2, b2, c, PP, H2, HH);
    }
    ln_reduce1<<<RED_BLOCKS, 256>>>(c, nPH2, part);
    ln_reduce2<<<1, 256>>>(part, (unsigned long long)nPH2, stats);
    ln_apply<<<(unsigned)((nPH2 + 255) / 256), 256>>>(c, ln2w, ln2b, stats, d, nPH2);

    // L3 + ReLU -> full LN
    {
        dim3 grid(H2 / 128, (PP + 127) / 128);
        sgemm_nt<1><<<grid, 256>>>(d, W3, b3, c, PP, H2, H2);
    }
    ln_reduce1<<<RED_BLOCKS, 256>>>(c, nPH2, part);
    ln_reduce2<<<1, 256>>>(part, (unsigned long long)nPH2, stats);
    ln_apply<<<(unsigned)((nPH2 + 255) / 256), 256>>>(c, ln3w, ln3b, stats, d, nPH2);

    // final dot + sigmoid
    final_dot_kernel<<<(PP + 7) / 8, 256>>>(d, W4, b4, vals);

    // assemble symmetric output
    zero_out_kernel<<<(NN * NN + 255) / 256, 256>>>(out);
    scatter_kernel<<<(PP + 255) / 256, 256>>>(vals, iu, ju, out);
}

// round 8
// speedup vs baseline: 1.8807x; 1.8807x over previous
#include <cuda_runtime.h>
#include <cuda_bf16.h>
#include <cstdint>
#include <math.h>

#define NN   84
#define PP   3486
#define MPAD 3584           // 28 * 128
#define HH   2048
#define H2   1024
#define G3   (3*HH)         // 6144
#define LN_EPS 1e-5f
#define RED_BLOCKS 1024

// ===================== scratch (device globals) ==============================
__device__ float g_gi[(size_t)NN * G3];
__device__ float g_gh[(size_t)MPAD * G3];
__device__ float g_h1[(size_t)PP * HH];
__device__ float g_h2[(size_t)PP * HH];
__device__ float g_a [(size_t)MPAD * HH];
__device__ float g_c [(size_t)MPAD * H2];
__device__ float g_d [(size_t)PP * H2];
__device__ __nv_bfloat16 g_ahi[(size_t)MPAD * HH];
__device__ __nv_bfloat16 g_alo[(size_t)MPAD * HH];
__device__ __nv_bfloat16 g_whh_hi[(size_t)G3 * HH];
__device__ __nv_bfloat16 g_whh_lo[(size_t)G3 * HH];
__device__ __nv_bfloat16 g_w1_hi[(size_t)HH * HH];
__device__ __nv_bfloat16 g_w1_lo[(size_t)HH * HH];
__device__ __nv_bfloat16 g_w2_hi[(size_t)H2 * HH];
__device__ __nv_bfloat16 g_w2_lo[(size_t)H2 * HH];
__device__ __nv_bfloat16 g_w3_hi[(size_t)H2 * H2];
__device__ __nv_bfloat16 g_w3_lo[(size_t)H2 * H2];
__device__ float  g_vals[PP];
__device__ int    g_iu[PP];
__device__ int    g_ju[PP];
__device__ double g_part[2 * RED_BLOCKS];
__device__ float  g_stats[2];

// ===================== baseline (non-arch-specific) PTX helpers ==============
__device__ __forceinline__ uint32_t smem_u32(const void* p) {
    uint32_t a;
    asm("{ .reg .u64 t; cvta.to.shared.u64 t, %1; cvt.u32.u64 %0, t; }" : "=r"(a) : "l"(p));
    return a;
}
__device__ __forceinline__ void cp16(uint32_t dst, const void* src) {
    asm volatile("cp.async.cg.shared.global [%0], [%1], 16;" :: "r"(dst), "l"(src));
}
__device__ __forceinline__ void cp_commit() {
    asm volatile("cp.async.commit_group;" ::: "memory");
}
__device__ __forceinline__ void cp_wait1() {
    asm volatile("cp.async.wait_group 1;" ::: "memory");
}
__device__ __forceinline__ void cp_wait0() {
    asm volatile("cp.async.wait_group 0;" ::: "memory");
}
__device__ __forceinline__ void ldsm4(uint32_t* r, uint32_t addr) {
    asm volatile("ldmatrix.sync.aligned.m8n8.x4.shared.b16 {%0,%1,%2,%3}, [%4];"
                 : "=r"(r[0]), "=r"(r[1]), "=r"(r[2]), "=r"(r[3]) : "r"(addr));
}
__device__ __forceinline__ void mma_bf16(float* d, const uint32_t* a, uint32_t b0, uint32_t b1) {
    asm volatile("mma.sync.aligned.m16n8k16.row.col.f32.bf16.bf16.f32 "
                 "{%0,%1,%2,%3}, {%4,%5,%6,%7}, {%8,%9}, {%0,%1,%2,%3};"
                 : "+f"(d[0]), "+f"(d[1]), "+f"(d[2]), "+f"(d[3])
                 : "r"(a[0]), "r"(a[1]), "r"(a[2]), "r"(a[3]), "r"(b0), "r"(b1));
}

// ===================== split-bf16 tensor-core GEMM ===========================
// C[MPAD,Nc] = A[MPAD,K] @ W[Nc,K]^T + bias, opt ReLU.
// A hi/lo bf16 (rows padded to MPAD), W hi/lo bf16. CTA tile 128x128,
// warps 4(M)x2(N), each 32x64. K in 32-chunks, cp.async double-buffered.
// Three fused compensation streams: hi*hi + lo*hi + hi*lo into fp32 regs.

#define ROW_B     80                      // bytes per smem tile row (64 data + 16 pad)
#define TILE_B    (128 * ROW_B)           // 10240
#define STAGE_B   (4 * TILE_B)            // 40960
#define GEMM_SMEM (2 * STAGE_B)           // 81920

template<int RELU>
__global__ __launch_bounds__(256, 2)
void mma_gemm(const __nv_bfloat16* __restrict__ Ahi, const __nv_bfloat16* __restrict__ Alo,
              const __nv_bfloat16* __restrict__ Whi, const __nv_bfloat16* __restrict__ Wlo,
              const float* __restrict__ bias, float* __restrict__ C,
              int Nc, int K)
{
    extern __shared__ char sm[];
    const uint32_t sbase = smem_u32(sm);
    const int tid  = threadIdx.x;
    const int w    = tid >> 5;
    const int lane = tid & 31;
    const int bm   = blockIdx.y * 128;
    const int bn   = blockIdx.x * 128;

    // ---- loader assignment: tile = w/2, 64 rows per warp, rows lane & lane+32
    const int ltile = w >> 1;
    const int lrow0 = ((w & 1) << 6) + lane;
    const __nv_bfloat16* lbase;
    int lgr;
    if      (ltile == 0) { lbase = Ahi; lgr = bm; }
    else if (ltile == 1) { lbase = Alo; lgr = bm; }
    else if (ltile == 2) { lbase = Whi; lgr = bn; }
    else                 { lbase = Wlo; lgr = bn; }

    const int KC = K >> 5;

    // ---- compute assignment
    const int wm = w >> 1;       // 0..3  (rows wm*32)
    const int wn = w & 1;        // 0..1  (cols wn*64)

    float acc[2][8][4];
    #pragma unroll
    for (int m = 0; m < 2; m++)
        #pragma unroll
        for (int n = 0; n < 8; n++)
            #pragma unroll
            for (int q = 0; q < 4; q++) acc[m][n][q] = 0.f;

    // precomputed ldmatrix smem offsets (within a stage)
    const uint32_t a_off0 = (uint32_t)(wm * 32 + (lane & 15)) * ROW_B + ((lane >> 4) << 4);
    const uint32_t b_row  = (uint32_t)(wn * 64 + ((lane >> 4) << 3) + (lane & 7));
    const uint32_t b_off0 = b_row * ROW_B + (((lane >> 3) & 1) << 4);

    // ---- prologue: load chunk 0 into stage 0
    {
        const char* g = (const char*)(lbase + (size_t)(lgr + lrow0) * K);
        const char* g2 = (const char*)(lbase + (size_t)(lgr + lrow0 + 32) * K);
        uint32_t sd  = sbase + ltile * TILE_B + lrow0 * ROW_B;
        uint32_t sd2 = sd + 32 * ROW_B;
        #pragma unroll
        for (int s = 0; s < 4; s++) { cp16(sd + s * 16, g + s * 16); cp16(sd2 + s * 16, g2 + s * 16); }
        cp_commit();
    }

    for (int c = 0; c < KC; c++) {
        if (c + 1 < KC) {
            const int k0 = (c + 1) << 5;
            const uint32_t sb = sbase + ((c + 1) & 1) * STAGE_B + ltile * TILE_B;
            const char* g  = (const char*)(lbase + (size_t)(lgr + lrow0) * K + k0);
            const char* g2 = (const char*)(lbase + (size_t)(lgr + lrow0 + 32) * K + k0);
            uint32_t sd  = sb + lrow0 * ROW_B;
            uint32_t sd2 = sd + 32 * ROW_B;
            #pragma unroll
            for (int s = 0; s < 4; s++) { cp16(sd + s * 16, g + s * 16); cp16(sd2 + s * 16, g2 + s * 16); }
            cp_commit();
            cp_wait1();
        } else {
            cp_wait0();
        }
        __syncthreads();

        const uint32_t st = sbase + (c & 1) * STAGE_B;
        const uint32_t Ah = st;
        const uint32_t Al = st + TILE_B;
        const uint32_t Bh = st + 2 * TILE_B;
        const uint32_t Bl = st + 3 * TILE_B;

        #pragma unroll
        for (int kk = 0; kk < 2; kk++) {
            uint32_t ah[2][4], al[2][4];
            #pragma unroll
            for (int m = 0; m < 2; m++) {
                uint32_t off = a_off0 + (uint32_t)(m * 16) * ROW_B + kk * 32;
                ldsm4(ah[m], Ah + off);
                ldsm4(al[m], Al + off);
            }
            #pragma unroll
            for (int np = 0; np < 4; np++) {
                uint32_t off = b_off0 + (uint32_t)(np * 16) * ROW_B + kk * 32;
                uint32_t bh[4], bl[4];
                ldsm4(bh, Bh + off);
                ldsm4(bl, Bl + off);
                #pragma unroll
                for (int t = 0; t < 2; t++) {
                    const int n = np * 2 + t;
                    #pragma unroll
                    for (int m = 0; m < 2; m++) {
                        mma_bf16(acc[m][n], ah[m], bh[t*2], bh[t*2+1]);
                        mma_bf16(acc[m][n], al[m], bh[t*2], bh[t*2+1]);
                        mma_bf16(acc[m][n], ah[m], bl[t*2], bl[t*2+1]);
                    }
                }
            }
        }
        __syncthreads();
    }

    // ---- epilogue: bias (+ReLU), direct global stores
    #pragma unroll
    for (int m = 0; m < 2; m++) {
        const int row = bm + wm * 32 + m * 16 + (lane >> 2);
        #pragma unroll
        for (int n = 0; n < 8; n++) {
            const int col = bn + wn * 64 + n * 8 + ((lane & 3) << 1);
            const float bx = bias[col], by = bias[col + 1];
            float2 v0, v1;
            v0.x = acc[m][n][0] + bx; v0.y = acc[m][n][1] + by;
            v1.x = acc[m][n][2] + bx; v1.y = acc[m][n][3] + by;
            if (RELU) {
                v0.x = fmaxf(v0.x, 0.f); v0.y = fmaxf(v0.y, 0.f);
                v1.x = fmaxf(v1.x, 0.f); v1.y = fmaxf(v1.y, 0.f);
            }
            *(float2*)(C + (size_t)row * Nc + col)       = v0;
            *(float2*)(C + (size_t)(row + 8) * Nc + col) = v1;
        }
    }
}

// ===================== small fp32 SGEMM (gi only) ============================
__global__ __launch_bounds__(256, 2)
void sgemm_nt(const float* __restrict__ A, const float* __restrict__ W,
              const float* __restrict__ bias, float* __restrict__ C,
              int M, int Nc, int K)
{
    __shared__ float As[16][128];
    __shared__ float Bs[16][128];
    const int tid = threadIdx.x;
    const int bm = blockIdx.y * 128, bn = blockIdx.x * 128;
    const int lrow = tid >> 1, lk = (tid & 1) << 3;
    const int rm = (tid >> 4) << 3, rn = (tid & 15) << 3;
    float acc[8][8];
    #pragma unroll
    for (int i = 0; i < 8; i++)
        #pragma unroll
        for (int j = 0; j < 8; j++) acc[i][j] = 0.f;
    const bool arow_ok = (bm + lrow) < M;
    const float* Ap = A + (size_t)(bm + lrow) * K + lk;
    const float* Wp = W + (size_t)(bn + lrow) * K + lk;
    for (int k0 = 0; k0 < K; k0 += 16) {
        float4 a0 = make_float4(0.f, 0.f, 0.f, 0.f), a1 = a0;
        if (arow_ok) { a0 = *(const float4*)(Ap + k0); a1 = *(const float4*)(Ap + k0 + 4); }
        float4 b0 = *(const float4*)(Wp + k0);
        float4 b1 = *(const float4*)(Wp + k0 + 4);
        __syncthreads();
        As[lk+0][lrow]=a0.x; As[lk+1][lrow]=a0.y; As[lk+2][lrow]=a0.z; As[lk+3][lrow]=a0.w;
        As[lk+4][lrow]=a1.x; As[lk+5][lrow]=a1.y; As[lk+6][lrow]=a1.z; As[lk+7][lrow]=a1.w;
        Bs[lk+0][lrow]=b0.x; Bs[lk+1][lrow]=b0.y; Bs[lk+2][lrow]=b0.z; Bs[lk+3][lrow]=b0.w;
        Bs[lk+4][lrow]=b1.x; Bs[lk+5][lrow]=b1.y; Bs[lk+6][lrow]=b1.z; Bs[lk+7][lrow]=b1.w;
        __syncthreads();
        #pragma unroll
        for (int kk = 0; kk < 16; kk++) {
            float4 av0 = *(const float4*)&As[kk][rm];
            float4 av1 = *(const float4*)&As[kk][rm + 4];
            float4 bv0 = *(const float4*)&Bs[kk][rn];
            float4 bv1 = *(const float4*)&Bs[kk][rn + 4];
            float a[8] = {av0.x,av0.y,av0.z,av0.w,av1.x,av1.y,av1.z,av1.w};
            float b[8] = {bv0.x,bv0.y,bv0.z,bv0.w,bv1.x,bv1.y,bv1.z,bv1.w};
            #pragma unroll
            for (int i = 0; i < 8; i++)
                #pragma unroll
                for (int j = 0; j < 8; j++)
                    acc[i][j] = fmaf(a[i], b[j], acc[i][j]);
        }
    }
    #pragma unroll
    for (int i = 0; i < 8; i++) {
        int row = bm + rm + i;
        if (row >= M) continue;
        float* Cp = C + (size_t)row * Nc + bn + rn;
        #pragma unroll
        for (int j = 0; j < 8; j++) Cp[j] = acc[i][j] + bias[bn + rn + j];
    }
}

// ===================== elementwise kernels ===================================
__global__ void make_pairs_kernel(int* __restrict__ iu, int* __restrict__ ju) {
    int p = blockIdx.x * blockDim.x + threadIdx.x;
    if (p >= PP) return;
    int off = 0;
    for (int i = 0; i < NN - 1; i++) {
        int cnt = NN - 1 - i;
        if (p < off + cnt) { iu[p] = i; ju[p] = i + 1 + (p - off); return; }
        off += cnt;
    }
}

__global__ void split_kernel(const float* __restrict__ x,
                             __nv_bfloat16* __restrict__ hi, __nv_bfloat16* __restrict__ lo,
                             size_t n, size_t npad)
{
    size_t i = (size_t)blockIdx.x * blockDim.x + threadIdx.x;
    if (i >= npad) return;
    float v = (i < n) ? x[i] : 0.f;
    __nv_bfloat16 h = __float2bfloat16(v);
    hi[i] = h;
    lo[i] = __float2bfloat16(v - __bfloat162float(h));
}

__device__ __forceinline__ float sigmoidf_(float x) { return 1.f / (1.f + expf(-x)); }

__global__ void gru_combine_split(const float* __restrict__ gh, const float* __restrict__ gi,
                                  const int* __restrict__ node_idx, const float* __restrict__ hprev,
                                  float* __restrict__ hout,
                                  __nv_bfloat16* __restrict__ ahi, __nv_bfloat16* __restrict__ alo)
{
    size_t idx = (size_t)blockIdx.x * blockDim.x + threadIdx.x;
    if (idx >= (size_t)MPAD * HH) return;
    if (idx >= (size_t)PP * HH) {
        ahi[idx] = __float2bfloat16(0.f);
        alo[idx] = __float2bfloat16(0.f);
        return;
    }
    int p = (int)(idx >> 11);
    int j = (int)(idx & 2047);
    int q = node_idx[p];
    const float* gip = gi + (size_t)q * G3;
    const float* ghp = gh + (size_t)p * G3;
    float r  = sigmoidf_(gip[j]        + ghp[j]);
    float z  = sigmoidf_(gip[j + HH]   + ghp[j + HH]);
    float nv = tanhf   (gip[j + 2*HH]  + r * ghp[j + 2*HH]);
    float h = hprev[idx];
    float o = (1.f - z) * nv + z * h;
    hout[idx] = o;
    __nv_bfloat16 hb = __float2bfloat16(o);
    ahi[idx] = hb;
    alo[idx] = __float2bfloat16(o - __bfloat162float(hb));
}

__global__ void ln_reduce1(const float* __restrict__ x, size_t n, double* __restrict__ part) {
    double s = 0.0, ss = 0.0;
    size_t stride = (size_t)gridDim.x * blockDim.x;
    for (size_t i = (size_t)blockIdx.x * blockDim.x + threadIdx.x; i < n; i += stride) {
        double v = (double)x[i];
        s += v; ss += v * v;
    }
    __shared__ double sh[256], sh2[256];
    sh[threadIdx.x] = s; sh2[threadIdx.x] = ss;
    __syncthreads();
    for (int o = 128; o > 0; o >>= 1) {
        if (threadIdx.x < o) { sh[threadIdx.x] += sh[threadIdx.x+o]; sh2[threadIdx.x] += sh2[threadIdx.x+o]; }
        __syncthreads();
    }
    if (threadIdx.x == 0) { part[blockIdx.x] = sh[0]; part[RED_BLOCKS + blockIdx.x] = sh2[0]; }
}

__global__ void ln_reduce2(const double* __restrict__ part, unsigned long long n,
                           float* __restrict__ stats) {
    __shared__ double sh[256], sh2[256];
    double s = 0.0, ss = 0.0;
    for (int i = threadIdx.x; i < RED_BLOCKS; i += 256) { s += part[i]; ss += part[RED_BLOCKS + i]; }
    sh[threadIdx.x] = s; sh2[threadIdx.x] = ss;
    __syncthreads();
    for (int o = 128; o > 0; o >>= 1) {
        if (threadIdx.x < o) { sh[threadIdx.x] += sh[threadIdx.x+o]; sh2[threadIdx.x] += sh2[threadIdx.x+o]; }
        __syncthreads();
    }
    if (threadIdx.x == 0) {
        double inv = 1.0 / (double)n;
        double mu = sh[0] * inv;
        double var = sh2[0] * inv - mu * mu;
        stats[0] = (float)mu;
        stats[1] = (float)(1.0 / sqrt(var + (double)LN_EPS));
    }
}

__global__ void ln_apply_split(const float* __restrict__ x, const float* __restrict__ w,
                               const float* __restrict__ b, const float* __restrict__ stats,
                               __nv_bfloat16* __restrict__ hi, __nv_bfloat16* __restrict__ lo,
                               size_t n, size_t npad)
{
    size_t i = (size_t)blockIdx.x * blockDim.x + threadIdx.x;
    if (i >= npad) return;
    float v = 0.f;
    if (i < n) {
        float mu = stats[0], rs = stats[1];
        v = (x[i] - mu) * rs * w[i] + b[i];
    }
    __nv_bfloat16 h = __float2bfloat16(v);
    hi[i] = h;
    lo[i] = __float2bfloat16(v - __bfloat162float(h));
}

__global__ void ln_apply(const float* __restrict__ x, const float* __restrict__ w,
                         const float* __restrict__ b, const float* __restrict__ stats,
                         float* __restrict__ y, size_t n)
{
    size_t i = (size_t)blockIdx.x * blockDim.x + threadIdx.x;
    if (i >= n) return;
    float mu = stats[0], rs = stats[1];
    y[i] = (x[i] - mu) * rs * w[i] + b[i];
}

__global__ void final_dot_kernel(const float* __restrict__ h, const float* __restrict__ W4,
                                 const float* __restrict__ b4, float* __restrict__ vals)
{
    int p = blockIdx.x * 8 + (threadIdx.x >> 5);
    int lane = threadIdx.x & 31;
    if (p >= PP) return;
    const float4* hp = (const float4*)(h + (size_t)p * H2);
    const float4* wp = (const float4*)W4;
    float s = 0.f;
    #pragma unroll
    for (int i = lane; i < H2 / 4; i += 32) {
        float4 a = hp[i], w = wp[i];
        s += a.x*w.x + a.y*w.y + a.z*w.z + a.w*w.w;
    }
    #pragma unroll
    for (int o = 16; o > 0; o >>= 1) s += __shfl_xor_sync(0xffffffffu, s, o);
    if (lane == 0) vals[p] = 1.f / (1.f + expf(-(s + b4[0])));
}

__global__ void zero_out_kernel(float* __restrict__ out) {
    int i = blockIdx.x * blockDim.x + threadIdx.x;
    if (i < NN * NN) out[i] = 0.f;
}

__global__ void scatter_kernel(const float* __restrict__ vals, const int* __restrict__ iu,
                               const int* __restrict__ ju, float* __restrict__ out)
{
    int p = blockIdx.x * blockDim.x + threadIdx.x;
    if (p >= PP) return;
    float v = vals[p];
    int i = iu[p], j = ju[p];
    out[i * NN + j] = v;
    out[j * NN + i] = v;
}

// ===================== driver ================================================
extern "C" void kernel_launch(void* const* d_in, const int* in_sizes, int n_in,
                              void* d_out, int out_size)
{
    const float* x    = (const float*)d_in[0];
    const float* hid  = (const float*)d_in[1];
    const float* Wih  = (const float*)d_in[2];
    const float* Whh  = (const float*)d_in[3];
    const float* bih  = (const float*)d_in[4];
    const float* bhh  = (const float*)d_in[5];
    const float* W1   = (const float*)d_in[6];
    const float* b1   = (const float*)d_in[7];
    const float* ln1w = (const float*)d_in[8];
    const float* ln1b = (const float*)d_in[9];
    const float* W2   = (const float*)d_in[10];
    const float* b2   = (const float*)d_in[11];
    const float* ln2w = (const float*)d_in[12];
    const float* ln2b = (const float*)d_in[13];
    const float* W3   = (const float*)d_in[14];
    const float* b3   = (const float*)d_in[15];
    const float* ln3w = (const float*)d_in[16];
    const float* ln3b = (const float*)d_in[17];
    const float* W4   = (const float*)d_in[18];
    const float* b4   = (const float*)d_in[19];
    float* out = (float*)d_out;

    float *gi, *gh, *h1, *h2, *a, *c, *d, *vals, *stats;
    __nv_bfloat16 *ahi, *alo, *whhh, *whhl, *w1h, *w1l, *w2h, *w2l, *w3h, *w3l;
    int *iu, *ju;
    double* part;
    cudaGetSymbolAddress((void**)&gi,    g_gi);
    cudaGetSymbolAddress((void**)&gh,    g_gh);
    cudaGetSymbolAddress((void**)&h1,    g_h1);
    cudaGetSymbolAddress((void**)&h2,    g_h2);
    cudaGetSymbolAddress((void**)&a,     g_a);
    cudaGetSymbolAddress((void**)&c,     g_c);
    cudaGetSymbolAddress((void**)&d,     g_d);
    cudaGetSymbolAddress((void**)&ahi,   g_ahi);
    cudaGetSymbolAddress((void**)&alo,   g_alo);
    cudaGetSymbolAddress((void**)&whhh,  g_whh_hi);
    cudaGetSymbolAddress((void**)&whhl,  g_whh_lo);
    cudaGetSymbolAddress((void**)&w1h,   g_w1_hi);
    cudaGetSymbolAddress((void**)&w1l,   g_w1_lo);
    cudaGetSymbolAddress((void**)&w2h,   g_w2_hi);
    cudaGetSymbolAddress((void**)&w2l,   g_w2_lo);
    cudaGetSymbolAddress((void**)&w3h,   g_w3_hi);
    cudaGetSymbolAddress((void**)&w3l,   g_w3_lo);
    cudaGetSymbolAddress((void**)&vals,  g_vals);
    cudaGetSymbolAddress((void**)&iu,    g_iu);
    cudaGetSymbolAddress((void**)&ju,    g_ju);
    cudaGetSymbolAddress((void**)&part,  g_part);
    cudaGetSymbolAddress((void**)&stats, g_stats);

    cudaFuncSetAttribute(mma_gemm<0>, cudaFuncAttributeMaxDynamicSharedMemorySize, GEMM_SMEM);
    cudaFuncSetAttribute(mma_gemm<1>, cudaFuncAttributeMaxDynamicSharedMemorySize, GEMM_SMEM);

    const size_t nPH   = (size_t)PP * HH;
    const size_t nPH2  = (size_t)PP * H2;
    const size_t padH  = (size_t)MPAD * HH;
    const size_t padH2 = (size_t)MPAD * H2;

    make_pairs_kernel<<<(PP + 255) / 256, 256>>>(iu, ju);

    // weight hi/lo splits
    split_kernel<<<(unsigned)(((size_t)G3*HH + 255) / 256), 256>>>(Whh, whhh, whhl, (size_t)G3*HH, (size_t)G3*HH);
    split_kernel<<<(unsigned)(((size_t)HH*HH + 255) / 256), 256>>>(W1,  w1h,  w1l,  (size_t)HH*HH, (size_t)HH*HH);
    split_kernel<<<(unsigned)(((size_t)H2*HH + 255) / 256), 256>>>(W2,  w2h,  w2l,  (size_t)H2*HH, (size_t)H2*HH);
    split_kernel<<<(unsigned)(((size_t)H2*H2 + 255) / 256), 256>>>(W3,  w3h,  w3l,  (size_t)H2*H2, (size_t)H2*H2);

    // gi = x @ Wih^T + bih  (tiny fp32 GEMM)
    {
        dim3 grid(G3 / 128, 1);
        sgemm_nt<<<grid, 256>>>(x, Wih, bih, gi, NN, G3, 64);
    }

    // GRU step 1
    split_kernel<<<(unsigned)((padH + 255) / 256), 256>>>(hid, ahi, alo, nPH, padH);
    {
        dim3 grid(G3 / 128, MPAD / 128);
        mma_gemm<0><<<grid, 256, GEMM_SMEM>>>(ahi, alo, whhh, whhl, bhh, gh, G3, HH);
    }
    gru_combine_split<<<(unsigned)((padH + 255) / 256), 256>>>(gh, gi, iu, hid, h1, ahi, alo);

    // GRU step 2
    {
        dim3 grid(G3 / 128, MPAD / 128);
        mma_gemm<0><<<grid, 256, GEMM_SMEM>>>(ahi, alo, whhh, whhl, bhh, gh, G3, HH);
    }
    gru_combine_split<<<(unsigned)((padH + 255) / 256), 256>>>(gh, gi, ju, h1, h2, ahi, alo);

    // L1 + ReLU -> full LN -> split
    {
        dim3 grid(HH / 128, MPAD / 128);
        mma_gemm<1><<<grid, 256, GEMM_SMEM>>>(ahi, alo, w1h, w1l, b1, a, HH, HH);
    }
    ln_reduce1<<<RED_BLOCKS, 256>>>(a, nPH, part);
    ln_reduce2<<<1, 256>>>(part, (unsigned long long)nPH, stats);
    ln_apply_split<<<(unsigned)((padH + 255) / 256), 256>>>(a, ln1w, ln1b, stats, ahi, alo, nPH, padH);

    // L2 + ReLU -> full LN -> split
    {
        dim3 grid(H2 / 128, MPAD / 128);
        mma_gemm<1><<<grid, 256, GEMM_SMEM>>>(ahi, alo, w2h, w2l, b2, c, H2, HH);
    }
    ln_reduce1<<<RED_BLOCKS, 256>>>(c, nPH2, part);
    ln_reduce2<<<1, 256>>>(part, (unsigned long long)nPH2, stats);
    ln_apply_split<<<(unsigned)((padH2 + 255) / 256), 256>>>(c, ln2w, ln2b, stats, ahi, alo, nPH2, padH2);

    // L3 + ReLU -> full LN (fp32 out)
    {
        dim3 grid(H2 / 128, MPAD / 128);
        mma_gemm<1><<<grid, 256, GEMM_SMEM>>>(ahi, alo, w3h, w3l, b3, c, H2, H2);
    }
    ln_reduce1<<<RED_BLOCKS, 256>>>(c, nPH2, part);
    ln_reduce2<<<1, 256>>>(part, (unsigned long long)nPH2, stats);
    ln_apply<<<(unsigned)((nPH2 + 255) / 256), 256>>>(c, ln3w, ln3b, stats, d, nPH2);

    // final dot + sigmoid, symmetric scatter
    final_dot_kernel<<<(PP + 7) / 8, 256>>>(d, W4, b4, vals);
    zero_out_kernel<<<(NN * NN + 255) / 256, 256>>>(out);
    scatter_kernel<<<(PP + 255) / 256, 256>>>(vals, iu, ju, out);
}

// round 9
// speedup vs baseline: 3.4576x; 1.8385x over previous
#include <cuda_runtime.h>
#include <cuda_fp16.h>
#include <cstdint>
#include <math.h>

#define NN   84
#define PP   3486
#define MPAD 3584           // 28 * 128
#define HH   2048
#define H2   1024
#define G3   (3*HH)         // 6144
#define LN_EPS 1e-5f
#define RED_BLOCKS 1024

// ===================== scratch (device globals) ==============================
__device__ float g_gi[(size_t)NN * G3];
__device__ float g_gh[(size_t)MPAD * G3];
__device__ float g_h1[(size_t)PP * HH];
__device__ float g_h2[(size_t)PP * HH];
__device__ float g_a [(size_t)MPAD * HH];
__device__ float g_c [(size_t)MPAD * H2];
__device__ float g_d [(size_t)PP * H2];
__device__ __half g_ahi[(size_t)MPAD * HH];
__device__ __half g_alo[(size_t)MPAD * HH];
__device__ __half g_whh[(size_t)G3 * HH];
__device__ __half g_w1 [(size_t)HH * HH];
__device__ __half g_w2 [(size_t)H2 * HH];
__device__ __half g_w3 [(size_t)H2 * H2];
__device__ float  g_vals[PP];
__device__ int    g_iu[PP];
__device__ int    g_ju[PP];
__device__ double g_part[2 * RED_BLOCKS];
__device__ float  g_stats[2];

// ===================== baseline PTX helpers ==================================
__device__ __forceinline__ uint32_t smem_u32(const void* p) {
    uint32_t a;
    asm("{ .reg .u64 t; cvta.to.shared.u64 t, %1; cvt.u32.u64 %0, t; }" : "=r"(a) : "l"(p));
    return a;
}
__device__ __forceinline__ void cp16(uint32_t dst, const void* src) {
    asm volatile("cp.async.cg.shared.global [%0], [%1], 16;" :: "r"(dst), "l"(src));
}
__device__ __forceinline__ void cp_commit() {
    asm volatile("cp.async.commit_group;" ::: "memory");
}
__device__ __forceinline__ void cp_wait1() {
    asm volatile("cp.async.wait_group 1;" ::: "memory");
}
__device__ __forceinline__ void ldsm4(uint32_t* r, uint32_t addr) {
    asm volatile("ldmatrix.sync.aligned.m8n8.x4.shared.b16 {%0,%1,%2,%3}, [%4];"
                 : "=r"(r[0]), "=r"(r[1]), "=r"(r[2]), "=r"(r[3]) : "r"(addr));
}
__device__ __forceinline__ void mma_f16(float* d, const uint32_t* a, uint32_t b0, uint32_t b1) {
    asm volatile("mma.sync.aligned.m16n8k16.row.col.f32.f16.f16.f32 "
                 "{%0,%1,%2,%3}, {%4,%5,%6,%7}, {%8,%9}, {%0,%1,%2,%3};"
                 : "+f"(d[0]), "+f"(d[1]), "+f"(d[2]), "+f"(d[3])
                 : "r"(a[0]), "r"(a[1]), "r"(a[2]), "r"(a[3]), "r"(b0), "r"(b1));
}

// ===================== split-fp16 tensor-core GEMM ===========================
// C[MPAD,Nc] = (Ahi+Alo)[MPAD,K] @ W16[Nc,K]^T + bias, opt ReLU.
// CTA tile 128x128, warps 4(M)x2(N), each 32x64. K in 32-chunks,
// 3-stage cp.async pipeline, one __syncthreads per chunk.
// Two MMA streams per fragment: Ahi*W + Alo*W (fp32 accum).

#define ROW_B     80                      // 64B data + 16B pad per smem row
#define TILE_B    (128 * ROW_B)           // 10240
#define STAGE_B   (3 * TILE_B)            // 30720  (Ahi, Alo, W)
#define NSTAGE    3
#define GEMM_SMEM (NSTAGE * STAGE_B)      // 92160

template<int RELU>
__global__ __launch_bounds__(256, 2)
void mma_gemm(const __half* __restrict__ Ahi, const __half* __restrict__ Alo,
              const __half* __restrict__ Wh,
              const float* __restrict__ bias, float* __restrict__ C,
              int Nc, int K)
{
    extern __shared__ char sm[];
    const uint32_t sbase = smem_u32(sm);
    const int tid  = threadIdx.x;
    const int w    = tid >> 5;
    const int lane = tid & 31;
    const int bm   = blockIdx.y * 128;
    const int bn   = blockIdx.x * 128;

    // ---- loader: 1536 cp16 ops per stage, 6 per thread ----
    const char* lsrc[6];
    uint32_t    ldst[6];
    #pragma unroll
    for (int i = 0; i < 6; i++) {
        const int o    = tid + i * 256;       // 0..1535
        const int tile = o >> 9;              // 0..2
        const int r    = (o >> 2) & 127;
        const int cq   = o & 3;
        const __half* base = (tile == 0) ? Ahi : (tile == 1) ? Alo : Wh;
        const int gr = (tile == 2) ? bn : bm;
        lsrc[i] = (const char*)(base + (size_t)(gr + r) * K) + cq * 16;
        ldst[i] = sbase + tile * TILE_B + r * ROW_B + cq * 16;
    }

    const int KC = K >> 5;

    // ---- compute assignment ----
    const int wm = w >> 1;       // 0..3
    const int wn = w & 1;        // 0..1

    float acc[2][8][4];
    #pragma unroll
    for (int m = 0; m < 2; m++)
        #pragma unroll
        for (int n = 0; n < 8; n++)
            #pragma unroll
            for (int q = 0; q < 4; q++) acc[m][n][q] = 0.f;

    const uint32_t a_off0 = (uint32_t)(wm * 32 + (lane & 15)) * ROW_B + ((lane >> 4) << 4);
    const uint32_t b_row  = (uint32_t)(wn * 64 + ((lane >> 4) << 3) + (lane & 7));
    const uint32_t b_off0 = b_row * ROW_B + (((lane >> 3) & 1) << 4);

    // ---- prologue: chunks 0, 1 into stages 0, 1 ----
    #pragma unroll
    for (int pc = 0; pc < 2; pc++) {
        const uint32_t so = pc * STAGE_B;
        const int kb = pc * 64;               // bytes: chunk*32 halves
        #pragma unroll
        for (int i = 0; i < 6; i++) cp16(ldst[i] + so, lsrc[i] + kb);
        cp_commit();
    }

    for (int c = 0; c < KC; c++) {
        cp_wait1();
        __syncthreads();

        if (c + 2 < KC) {
            const uint32_t so = ((c + 2) % NSTAGE) * STAGE_B;
            const int kb = (c + 2) * 64;
            #pragma unroll
            for (int i = 0; i < 6; i++) cp16(ldst[i] + so, lsrc[i] + kb);
        }
        cp_commit();

        const uint32_t st = sbase + (c % NSTAGE) * STAGE_B;
        const uint32_t Ah = st;
        const uint32_t Al = st + TILE_B;
        const uint32_t Bh = st + 2 * TILE_B;

        #pragma unroll
        for (int kk = 0; kk < 2; kk++) {
            uint32_t ah[2][4], al[2][4];
            #pragma unroll
            for (int m = 0; m < 2; m++) {
                uint32_t off = a_off0 + (uint32_t)(m * 16) * ROW_B + kk * 32;
                ldsm4(ah[m], Ah + off);
                ldsm4(al[m], Al + off);
            }
            #pragma unroll
            for (int np = 0; np < 4; np++) {
                uint32_t off = b_off0 + (uint32_t)(np * 16) * ROW_B + kk * 32;
                uint32_t bh[4];
                ldsm4(bh, Bh + off);
                #pragma unroll
                for (int t = 0; t < 2; t++) {
                    const int n = np * 2 + t;
                    #pragma unroll
                    for (int m = 0; m < 2; m++) {
                        mma_f16(acc[m][n], ah[m], bh[t*2], bh[t*2+1]);
                        mma_f16(acc[m][n], al[m], bh[t*2], bh[t*2+1]);
                    }
                }
            }
        }
    }

    // ---- epilogue: bias (+ReLU), direct stores ----
    #pragma unroll
    for (int m = 0; m < 2; m++) {
        const int row = bm + wm * 32 + m * 16 + (lane >> 2);
        #pragma unroll
        for (int n = 0; n < 8; n++) {
            const int col = bn + wn * 64 + n * 8 + ((lane & 3) << 1);
            const float bx = bias[col], by = bias[col + 1];
            float2 v0, v1;
            v0.x = acc[m][n][0] + bx; v0.y = acc[m][n][1] + by;
            v1.x = acc[m][n][2] + bx; v1.y = acc[m][n][3] + by;
            if (RELU) {
                v0.x = fmaxf(v0.x, 0.f); v0.y = fmaxf(v0.y, 0.f);
                v1.x = fmaxf(v1.x, 0.f); v1.y = fmaxf(v1.y, 0.f);
            }
            *(float2*)(C + (size_t)row * Nc + col)       = v0;
            *(float2*)(C + (size_t)(row + 8) * Nc + col) = v1;
        }
    }
}

// ===================== small fp32 SGEMM (gi only) ============================
__global__ __launch_bounds__(256, 2)
void sgemm_nt(const float* __restrict__ A, const float* __restrict__ W,
              const float* __restrict__ bias, float* __restrict__ C,
              int M, int Nc, int K)
{
    __shared__ float As[16][128];
    __shared__ float Bs[16][128];
    const int tid = threadIdx.x;
    const int bm = blockIdx.y * 128, bn = blockIdx.x * 128;
    const int lrow = tid >> 1, lk = (tid & 1) << 3;
    const int rm = (tid >> 4) << 3, rn = (tid & 15) << 3;
    float acc[8][8];
    #pragma unroll
    for (int i = 0; i < 8; i++)
        #pragma unroll
        for (int j = 0; j < 8; j++) acc[i][j] = 0.f;
    const bool arow_ok = (bm + lrow) < M;
    const float* Ap = A + (size_t)(bm + lrow) * K + lk;
    const float* Wp = W + (size_t)(bn + lrow) * K + lk;
    for (int k0 = 0; k0 < K; k0 += 16) {
        float4 a0 = make_float4(0.f, 0.f, 0.f, 0.f), a1 = a0;
        if (arow_ok) { a0 = *(const float4*)(Ap + k0); a1 = *(const float4*)(Ap + k0 + 4); }
        float4 b0 = *(const float4*)(Wp + k0);
        float4 b1 = *(const float4*)(Wp + k0 + 4);
        __syncthreads();
        As[lk+0][lrow]=a0.x; As[lk+1][lrow]=a0.y; As[lk+2][lrow]=a0.z; As[lk+3][lrow]=a0.w;
        As[lk+4][lrow]=a1.x; As[lk+5][lrow]=a1.y; As[lk+6][lrow]=a1.z; As[lk+7][lrow]=a1.w;
        Bs[lk+0][lrow]=b0.x; Bs[lk+1][lrow]=b0.y; Bs[lk+2][lrow]=b0.z; Bs[lk+3][lrow]=b0.w;
        Bs[lk+4][lrow]=b1.x; Bs[lk+5][lrow]=b1.y; Bs[lk+6][lrow]=b1.z; Bs[lk+7][lrow]=b1.w;
        __syncthreads();
        #pragma unroll
        for (int kk = 0; kk < 16; kk++) {
            float4 av0 = *(const float4*)&As[kk][rm];
            float4 av1 = *(const float4*)&As[kk][rm + 4];
            float4 bv0 = *(const float4*)&Bs[kk][rn];
            float4 bv1 = *(const float4*)&Bs[kk][rn + 4];
            float a[8] = {av0.x,av0.y,av0.z,av0.w,av1.x,av1.y,av1.z,av1.w};
            float b[8] = {bv0.x,bv0.y,bv0.z,bv0.w,bv1.x,bv1.y,bv1.z,bv1.w};
            #pragma unroll
            for (int i = 0; i < 8; i++)
                #pragma unroll
                for (int j = 0; j < 8; j++)
                    acc[i][j] = fmaf(a[i], b[j], acc[i][j]);
        }
    }
    #pragma unroll
    for (int i = 0; i < 8; i++) {
        int row = bm + rm + i;
        if (row >= M) continue;
        float* Cp = C + (size_t)row * Nc + bn + rn;
        #pragma unroll
        for (int j = 0; j < 8; j++) Cp[j] = acc[i][j] + bias[bn + rn + j];
    }
}

// ===================== elementwise kernels ===================================
__global__ void make_pairs_kernel(int* __restrict__ iu, int* __restrict__ ju) {
    int p = blockIdx.x * blockDim.x + threadIdx.x;
    if (p >= PP) return;
    int off = 0;
    for (int i = 0; i < NN - 1; i++) {
        int cnt = NN - 1 - i;
        if (p < off + cnt) { iu[p] = i; ju[p] = i + 1 + (p - off); return; }
        off += cnt;
    }
}

// weights: fp32 -> fp16 (round to nearest)
__global__ void wsplit_kernel(const float* __restrict__ x, __half* __restrict__ h, size_t n) {
    size_t i = (size_t)blockIdx.x * blockDim.x + threadIdx.x;
    if (i >= n) return;
    h[i] = __float2half(x[i]);
}

// activations: fp32 -> (hi, lo) fp16; zero-fills [n, npad)
__global__ void asplit_kernel(const float* __restrict__ x,
                              __half* __restrict__ hi, __half* __restrict__ lo,
                              size_t n, size_t npad)
{
    size_t i = (size_t)blockIdx.x * blockDim.x + threadIdx.x;
    if (i >= npad) return;
    float v = (i < n) ? x[i] : 0.f;
    __half h = __float2half(v);
    hi[i] = h;
    lo[i] = __float2half(v - __half2float(h));
}

__device__ __forceinline__ float sigmoidf_(float x) { return 1.f / (1.f + expf(-x)); }

__global__ void gru_combine_split(const float* __restrict__ gh, const float* __restrict__ gi,
                                  const int* __restrict__ node_idx, const float* __restrict__ hprev,
                                  float* __restrict__ hout,
                                  __half* __restrict__ ahi, __half* __restrict__ alo)
{
    size_t idx = (size_t)blockIdx.x * blockDim.x + threadIdx.x;
    if (idx >= (size_t)MPAD * HH) return;
    if (idx >= (size_t)PP * HH) {
        ahi[idx] = __float2half(0.f);
        alo[idx] = __float2half(0.f);
        return;
    }
    int p = (int)(idx >> 11);
    int j = (int)(idx & 2047);
    int q = node_idx[p];
    const float* gip = gi + (size_t)q * G3;
    const float* ghp = gh + (size_t)p * G3;
    float r  = sigmoidf_(gip[j]        + ghp[j]);
    float z  = sigmoidf_(gip[j + HH]   + ghp[j + HH]);
    float nv = tanhf   (gip[j + 2*HH]  + r * ghp[j + 2*HH]);
    float h = hprev[idx];
    float o = (1.f - z) * nv + z * h;
    hout[idx] = o;
    __half hb = __float2half(o);
    ahi[idx] = hb;
    alo[idx] = __float2half(o - __half2float(hb));
}

__global__ void ln_reduce1(const float* __restrict__ x, size_t n, double* __restrict__ part) {
    double s = 0.0, ss = 0.0;
    size_t stride = (size_t)gridDim.x * blockDim.x;
    for (size_t i = (size_t)blockIdx.x * blockDim.x + threadIdx.x; i < n; i += stride) {
        double v = (double)x[i];
        s += v; ss += v * v;
    }
    __shared__ double sh[256], sh2[256];
    sh[threadIdx.x] = s; sh2[threadIdx.x] = ss;
    __syncthreads();
    for (int o = 128; o > 0; o >>= 1) {
        if (threadIdx.x < o) { sh[threadIdx.x] += sh[threadIdx.x+o]; sh2[threadIdx.x] += sh2[threadIdx.x+o]; }
        __syncthreads();
    }
    if (threadIdx.x == 0) { part[blockIdx.x] = sh[0]; part[RED_BLOCKS + blockIdx.x] = sh2[0]; }
}

__global__ void ln_reduce2(const double* __restrict__ part, unsigned long long n,
                           float* __restrict__ stats) {
    __shared__ double sh[256], sh2[256];
    double s = 0.0, ss = 0.0;
    for (int i = threadIdx.x; i < RED_BLOCKS; i += 256) { s += part[i]; ss += part[RED_BLOCKS + i]; }
    sh[threadIdx.x] = s; sh2[threadIdx.x] = ss;
    __syncthreads();
    for (int o = 128; o > 0; o >>= 1) {
        if (threadIdx.x < o) { sh[threadIdx.x] += sh[threadIdx.x+o]; sh2[threadIdx.x] += sh2[threadIdx.x+o]; }
        __syncthreads();
    }
    if (threadIdx.x == 0) {
        double inv = 1.0 / (double)n;
        double mu = sh[0] * inv;
        double var = sh2[0] * inv - mu * mu;
        stats[0] = (float)mu;
        stats[1] = (float)(1.0 / sqrt(var + (double)LN_EPS));
    }
}

__global__ void ln_apply_split(const float* __restrict__ x, const float* __restrict__ w,
                               const float* __restrict__ b, const float* __restrict__ stats,
                               __half* __restrict__ hi, __half* __restrict__ lo,
                               size_t n, size_t npad)
{
    size_t i = (size_t)blockIdx.x * blockDim.x + threadIdx.x;
    if (i >= npad) return;
    float v = 0.f;
    if (i < n) {
        float mu = stats[0], rs = stats[1];
        v = (x[i] - mu) * rs * w[i] + b[i];
    }
    __half h = __float2half(v);
    hi[i] = h;
    lo[i] = __float2half(v - __half2float(h));
}

__global__ void ln_apply(const float* __restrict__ x, const float* __restrict__ w,
                         const float* __restrict__ b, const float* __restrict__ stats,
                         float* __restrict__ y, size_t n)
{
    size_t i = (size_t)blockIdx.x * blockDim.x + threadIdx.x;
    if (i >= n) return;
    float mu = stats[0], rs = stats[1];
    y[i] = (x[i] - mu) * rs * w[i] + b[i];
}

__global__ void final_dot_kernel(const float* __restrict__ h, const float* __restrict__ W4,
                                 const float* __restrict__ b4, float* __restrict__ vals)
{
    int p = blockIdx.x * 8 + (threadIdx.x >> 5);
    int lane = threadIdx.x & 31;
    if (p >= PP) return;
    const float4* hp = (const float4*)(h + (size_t)p * H2);
    const float4* wp = (const float4*)W4;
    float s = 0.f;
    #pragma unroll
    for (int i = lane; i < H2 / 4; i += 32) {
        float4 a = hp[i], w = wp[i];
        s += a.x*w.x + a.y*w.y + a.z*w.z + a.w*w.w;
    }
    #pragma unroll
    for (int o = 16; o > 0; o >>= 1) s += __shfl_xor_sync(0xffffffffu, s, o);
    if (lane == 0) vals[p] = 1.f / (1.f + expf(-(s + b4[0])));
}

__global__ void zero_out_kernel(float* __restrict__ out) {
    int i = blockIdx.x * blockDim.x + threadIdx.x;
    if (i < NN * NN) out[i] = 0.f;
}

__global__ void scatter_kernel(const float* __restrict__ vals, const int* __restrict__ iu,
                               const int* __restrict__ ju, float* __restrict__ out)
{
    int p = blockIdx.x * blockDim.x + threadIdx.x;
    if (p >= PP) return;
    float v = vals[p];
    int i = iu[p], j = ju[p];
    out[i * NN + j] = v;
    out[j * NN + i] = v;
}

// ===================== driver ================================================
extern "C" void kernel_launch(void* const* d_in, const int* in_sizes, int n_in,
                              void* d_out, int out_size)
{
    const float* x    = (const float*)d_in[0];
    const float* hid  = (const float*)d_in[1];
    const float* Wih  = (const float*)d_in[2];
    const float* Whh  = (const float*)d_in[3];
    const float* bih  = (const float*)d_in[4];
    const float* bhh  = (const float*)d_in[5];
    const float* W1   = (const float*)d_in[6];
    const float* b1   = (const float*)d_in[7];
    const float* ln1w = (const float*)d_in[8];
    const float* ln1b = (const float*)d_in[9];
    const float* W2   = (const float*)d_in[10];
    const float* b2   = (const float*)d_in[11];
    const float* ln2w = (const float*)d_in[12];
    const float* ln2b = (const float*)d_in[13];
    const float* W3   = (const float*)d_in[14];
    const float* b3   = (const float*)d_in[15];
    const float* ln3w = (const float*)d_in[16];
    const float* ln3b = (const float*)d_in[17];
    const float* W4   = (const float*)d_in[18];
    const float* b4   = (const float*)d_in[19];
    float* out = (float*)d_out;

    float *gi, *gh, *h1, *h2, *a, *c, *d, *vals, *stats;
    __half *ahi, *alo, *whh, *w1, *w2, *w3;
    int *iu, *ju;
    double* part;
    cudaGetSymbolAddress((void**)&gi,    g_gi);
    cudaGetSymbolAddress((void**)&gh,    g_gh);
    cudaGetSymbolAddress((void**)&h1,    g_h1);
    cudaGetSymbolAddress((void**)&h2,    g_h2);
    cudaGetSymbolAddress((void**)&a,     g_a);
    cudaGetSymbolAddress((void**)&c,     g_c);
    cudaGetSymbolAddress((void**)&d,     g_d);
    cudaGetSymbolAddress((void**)&ahi,   g_ahi);
    cudaGetSymbolAddress((void**)&alo,   g_alo);
    cudaGetSymbolAddress((void**)&whh,   g_whh);
    cudaGetSymbolAddress((void**)&w1,    g_w1);
    cudaGetSymbolAddress((void**)&w2,    g_w2);
    cudaGetSymbolAddress((void**)&w3,    g_w3);
    cudaGetSymbolAddress((void**)&vals,  g_vals);
    cudaGetSymbolAddress((void**)&iu,    g_iu);
    cudaGetSymbolAddress((void**)&ju,    g_ju);
    cudaGetSymbolAddress((void**)&part,  g_part);
    cudaGetSymbolAddress((void**)&stats, g_stats);

    cudaFuncSetAttribute(mma_gemm<0>, cudaFuncAttributeMaxDynamicSharedMemorySize, GEMM_SMEM);
    cudaFuncSetAttribute(mma_gemm<1>, cudaFuncAttributeMaxDynamicSharedMemorySize, GEMM_SMEM);

    const size_t nPH   = (size_t)PP * HH;
    const size_t nPH2  = (size_t)PP * H2;
    const size_t padH  = (size_t)MPAD * HH;
    const size_t padH2 = (size_t)MPAD * H2;

    make_pairs_kernel<<<(PP + 255) / 256, 256>>>(iu, ju);

    // weight fp16 conversion
    wsplit_kernel<<<(unsigned)(((size_t)G3*HH + 255) / 256), 256>>>(Whh, whh, (size_t)G3*HH);
    wsplit_kernel<<<(unsigned)(((size_t)HH*HH + 255) / 256), 256>>>(W1,  w1,  (size_t)HH*HH);
    wsplit_kernel<<<(unsigned)(((size_t)H2*HH + 255) / 256), 256>>>(W2,  w2,  (size_t)H2*HH);
    wsplit_kernel<<<(unsigned)(((size_t)H2*H2 + 255) / 256), 256>>>(W3,  w3,  (size_t)H2*H2);

    // gi = x @ Wih^T + bih  (tiny fp32 GEMM)
    {
        dim3 grid(G3 / 128, 1);
        sgemm_nt<<<grid, 256>>>(x, Wih, bih, gi, NN, G3, 64);
    }

    // GRU step 1
    asplit_kernel<<<(unsigned)((padH + 255) / 256), 256>>>(hid, ahi, alo, nPH, padH);
    {
        dim3 grid(G3 / 128, MPAD / 128);
        mma_gemm<0><<<grid, 256, GEMM_SMEM>>>(ahi, alo, whh, bhh, gh, G3, HH);
    }
    gru_combine_split<<<(unsigned)((padH + 255) / 256), 256>>>(gh, gi, iu, hid, h1, ahi, alo);

    // GRU step 2
    {
        dim3 grid(G3 / 128, MPAD / 128);
        mma_gemm<0><<<grid, 256, GEMM_SMEM>>>(ahi, alo, whh, bhh, gh, G3, HH);
    }
    gru_combine_split<<<(unsigned)((padH + 255) / 256), 256>>>(gh, gi, ju, h1, h2, ahi, alo);

    // L1 + ReLU -> full LN -> split
    {
        dim3 grid(HH / 128, MPAD / 128);
        mma_gemm<1><<<grid, 256, GEMM_SMEM>>>(ahi, alo, w1, b1, a, HH, HH);
    }
    ln_reduce1<<<RED_BLOCKS, 256>>>(a, nPH, part);
    ln_reduce2<<<1, 256>>>(part, (unsigned long long)nPH, stats);
    ln_apply_split<<<(unsigned)((padH + 255) / 256), 256>>>(a, ln1w, ln1b, stats, ahi, alo, nPH, padH);

    // L2 + ReLU -> full LN -> split
    {
        dim3 grid(H2 / 128, MPAD / 128);
        mma_gemm<1><<<grid, 256, GEMM_SMEM>>>(ahi, alo, w2, b2, c, H2, HH);
    }
    ln_reduce1<<<RED_BLOCKS, 256>>>(c, nPH2, part);
    ln_reduce2<<<1, 256>>>(part, (unsigned long long)nPH2, stats);
    ln_apply_split<<<(unsigned)((padH2 + 255) / 256), 256>>>(c, ln2w, ln2b, stats, ahi, alo, nPH2, padH2);

    // L3 + ReLU -> full LN (fp32 out)
    {
        dim3 grid(H2 / 128, MPAD / 128);
        mma_gemm<1><<<grid, 256, GEMM_SMEM>>>(ahi, alo, w3, b3, c, H2, H2);
    }
    ln_reduce1<<<RED_BLOCKS, 256>>>(c, nPH2, part);
    ln_reduce2<<<1, 256>>>(part, (unsigned long long)nPH2, stats);
    ln_apply<<<(unsigned)((nPH2 + 255) / 256), 256>>>(c, ln3w, ln3b, stats, d, nPH2);

    // final dot + sigmoid, symmetric scatter
    final_dot_kernel<<<(PP + 7) / 8, 256>>>(d, W4, b4, vals);
    zero_out_kernel<<<(NN * NN + 255) / 256, 256>>>(out);
    scatter_kernel<<<(PP + 255) / 256, 256>>>(vals, iu, ju, out);
}

// round 14
// speedup vs baseline: 3.7142x; 1.0742x over previous
#include <cuda_runtime.h>
#include <cuda_fp16.h>
#include <cstdint>
#include <math.h>

#define NN   84
#define PP   3486
#define MPAD 3584           // 28 * 128
#define HH   2048
#define H2   1024
#define G3   (3*HH)         // 6144
#define LN_EPS 1e-5f
#define RED_BLOCKS 1024

// ===================== scratch (device globals) ==============================
__device__ float g_gi[(size_t)NN * G3];
__device__ float g_gh[(size_t)MPAD * G3];
__device__ float g_h1[(size_t)PP * HH];
__device__ float g_a [(size_t)MPAD * HH];
__device__ float g_c [(size_t)MPAD * H2];
__device__ __half g_ahi[(size_t)MPAD * HH];
__device__ __half g_alo[(size_t)MPAD * HH];
__device__ __half g_whh[(size_t)G3 * HH];
__device__ __half g_w1 [(size_t)HH * HH];
__device__ __half g_w2 [(size_t)H2 * HH];
__device__ __half g_w3 [(size_t)H2 * H2];
__device__ float  g_vals[PP];
__device__ int    g_iu[PP];
__device__ int    g_ju[PP];
__device__ double g_part[2 * RED_BLOCKS];
__device__ float  g_stats[2];

// ===================== baseline PTX helpers ==================================
__device__ __forceinline__ uint32_t smem_u32(const void* p) {
    uint32_t a;
    asm("{ .reg .u64 t; cvta.to.shared.u64 t, %1; cvt.u32.u64 %0, t; }" : "=r"(a) : "l"(p));
    return a;
}
__device__ __forceinline__ void cp16(uint32_t dst, const void* src) {
    asm volatile("cp.async.cg.shared.global [%0], [%1], 16;" :: "r"(dst), "l"(src));
}
__device__ __forceinline__ void cp_commit() {
    asm volatile("cp.async.commit_group;" ::: "memory");
}
__device__ __forceinline__ void cp_wait1() {
    asm volatile("cp.async.wait_group 1;" ::: "memory");
}
__device__ __forceinline__ void ldsm4(uint32_t* r, uint32_t addr) {
    asm volatile("ldmatrix.sync.aligned.m8n8.x4.shared.b16 {%0,%1,%2,%3}, [%4];"
                 : "=r"(r[0]), "=r"(r[1]), "=r"(r[2]), "=r"(r[3]) : "r"(addr));
}
__device__ __forceinline__ void mma_f16(float* d, const uint32_t* a, uint32_t b0, uint32_t b1) {
    asm volatile("mma.sync.aligned.m16n8k16.row.col.f32.f16.f16.f32 "
                 "{%0,%1,%2,%3}, {%4,%5,%6,%7}, {%8,%9}, {%0,%1,%2,%3};"
                 : "+f"(d[0]), "+f"(d[1]), "+f"(d[2]), "+f"(d[3])
                 : "r"(a[0]), "r"(a[1]), "r"(a[2]), "r"(a[3]), "r"(b0), "r"(b1));
}

// pack 4 floats -> 2x half2 stored as uint2
__device__ __forceinline__ uint2 pack4h(float a, float b, float c, float d) {
    __half2 lo = __floats2half2_rn(a, b);
    __half2 hi = __floats2half2_rn(c, d);
    uint2 r;
    r.x = *(uint32_t*)&lo;
    r.y = *(uint32_t*)&hi;
    return r;
}

// ===================== split-fp16 tensor-core GEMM ===========================
#define ROW_B     80
#define TILE_B    (128 * ROW_B)
#define STAGE_B   (3 * TILE_B)
#define NSTAGE    3
#define GEMM_SMEM (NSTAGE * STAGE_B)      // 92160

template<int RELU>
__global__ __launch_bounds__(256, 2)
void mma_gemm(const __half* __restrict__ Ahi, const __half* __restrict__ Alo,
              const __half* __restrict__ Wh,
              const float* __restrict__ bias, float* __restrict__ C,
              int Nc, int K)
{
    extern __shared__ char sm[];
    const uint32_t sbase = smem_u32(sm);
    const int tid  = threadIdx.x;
    const int w    = tid >> 5;
    const int lane = tid & 31;
    const int bm   = blockIdx.y * 128;
    const int bn   = blockIdx.x * 128;

    const char* lsrc[6];
    uint32_t    ldst[6];
    #pragma unroll
    for (int i = 0; i < 6; i++) {
        const int o    = tid + i * 256;
        const int tile = o >> 9;
        const int r    = (o >> 2) & 127;
        const int cq   = o & 3;
        const __half* base = (tile == 0) ? Ahi : (tile == 1) ? Alo : Wh;
        const int gr = (tile == 2) ? bn : bm;
        lsrc[i] = (const char*)(base + (size_t)(gr + r) * K) + cq * 16;
        ldst[i] = sbase + tile * TILE_B + r * ROW_B + cq * 16;
    }

    const int KC = K >> 5;
    const int wm = w >> 1;
    const int wn = w & 1;

    float acc[2][8][4];
    #pragma unroll
    for (int m = 0; m < 2; m++)
        #pragma unroll
        for (int n = 0; n < 8; n++)
            #pragma unroll
            for (int q = 0; q < 4; q++) acc[m][n][q] = 0.f;

    const uint32_t a_off0 = (uint32_t)(wm * 32 + (lane & 15)) * ROW_B + ((lane >> 4) << 4);
    const uint32_t b_row  = (uint32_t)(wn * 64 + ((lane >> 4) << 3) + (lane & 7));
    const uint32_t b_off0 = b_row * ROW_B + (((lane >> 3) & 1) << 4);

    #pragma unroll
    for (int pc = 0; pc < 2; pc++) {
        const uint32_t so = pc * STAGE_B;
        const int kb = pc * 64;
        #pragma unroll
        for (int i = 0; i < 6; i++) cp16(ldst[i] + so, lsrc[i] + kb);
        cp_commit();
    }

    for (int c = 0; c < KC; c++) {
        cp_wait1();
        __syncthreads();

        if (c + 2 < KC) {
            const uint32_t so = ((c + 2) % NSTAGE) * STAGE_B;
            const int kb = (c + 2) * 64;
            #pragma unroll
            for (int i = 0; i < 6; i++) cp16(ldst[i] + so, lsrc[i] + kb);
        }
        cp_commit();

        const uint32_t st = sbase + (c % NSTAGE) * STAGE_B;
        const uint32_t Ah = st;
        const uint32_t Al = st + TILE_B;
        const uint32_t Bh = st + 2 * TILE_B;

        #pragma unroll
        for (int kk = 0; kk < 2; kk++) {
            uint32_t ah[2][4], al[2][4];
            #pragma unroll
            for (int m = 0; m < 2; m++) {
                uint32_t off = a_off0 + (uint32_t)(m * 16) * ROW_B + kk * 32;
                ldsm4(ah[m], Ah + off);
                ldsm4(al[m], Al + off);
            }
            #pragma unroll
            for (int np = 0; np < 4; np++) {
                uint32_t off = b_off0 + (uint32_t)(np * 16) * ROW_B + kk * 32;
                uint32_t bh[4];
                ldsm4(bh, Bh + off);
                #pragma unroll
                for (int t = 0; t < 2; t++) {
                    const int n = np * 2 + t;
                    #pragma unroll
                    for (int m = 0; m < 2; m++) {
                        mma_f16(acc[m][n], ah[m], bh[t*2], bh[t*2+1]);
                        mma_f16(acc[m][n], al[m], bh[t*2], bh[t*2+1]);
                    }
                }
            }
        }
    }

    #pragma unroll
    for (int m = 0; m < 2; m++) {
        const int row = bm + wm * 32 + m * 16 + (lane >> 2);
        #pragma unroll
        for (int n = 0; n < 8; n++) {
            const int col = bn + wn * 64 + n * 8 + ((lane & 3) << 1);
            const float bx = bias[col], by = bias[col + 1];
            float2 v0, v1;
            v0.x = acc[m][n][0] + bx; v0.y = acc[m][n][1] + by;
            v1.x = acc[m][n][2] + bx; v1.y = acc[m][n][3] + by;
            if (RELU) {
                v0.x = fmaxf(v0.x, 0.f); v0.y = fmaxf(v0.y, 0.f);
                v1.x = fmaxf(v1.x, 0.f); v1.y = fmaxf(v1.y, 0.f);
            }
            *(float2*)(C + (size_t)row * Nc + col)       = v0;
            *(float2*)(C + (size_t)(row + 8) * Nc + col) = v1;
        }
    }
}

// ===================== small fp32 SGEMM (gi only) ============================
__global__ __launch_bounds__(256, 2)
void sgemm_nt(const float* __restrict__ A, const float* __restrict__ W,
              const float* __restrict__ bias, float* __restrict__ C,
              int M, int Nc, int K)
{
    __shared__ float As[16][128];
    __shared__ float Bs[16][128];
    const int tid = threadIdx.x;
    const int bm = blockIdx.y * 128, bn = blockIdx.x * 128;
    const int lrow = tid >> 1, lk = (tid & 1) << 3;
    const int rm = (tid >> 4) << 3, rn = (tid & 15) << 3;
    float acc[8][8];
    #pragma unroll
    for (int i = 0; i < 8; i++)
        #pragma unroll
        for (int j = 0; j < 8; j++) acc[i][j] = 0.f;
    const bool arow_ok = (bm + lrow) < M;
    const float* Ap = A + (size_t)(bm + lrow) * K + lk;
    const float* Wp = W + (size_t)(bn + lrow) * K + lk;
    for (int k0 = 0; k0 < K; k0 += 16) {
        float4 a0 = make_float4(0.f, 0.f, 0.f, 0.f), a1 = a0;
        if (arow_ok) { a0 = *(const float4*)(Ap + k0); a1 = *(const float4*)(Ap + k0 + 4); }
        float4 b0 = *(const float4*)(Wp + k0);
        float4 b1 = *(const float4*)(Wp + k0 + 4);
        __syncthreads();
        As[lk+0][lrow]=a0.x; As[lk+1][lrow]=a0.y; As[lk+2][lrow]=a0.z; As[lk+3][lrow]=a0.w;
        As[lk+4][lrow]=a1.x; As[lk+5][lrow]=a1.y; As[lk+6][lrow]=a1.z; As[lk+7][lrow]=a1.w;
        Bs[lk+0][lrow]=b0.x; Bs[lk+1][lrow]=b0.y; Bs[lk+2][lrow]=b0.z; Bs[lk+3][lrow]=b0.w;
        Bs[lk+4][lrow]=b1.x; Bs[lk+5][lrow]=b1.y; Bs[lk+6][lrow]=b1.z; Bs[lk+7][lrow]=b1.w;
        __syncthreads();
        #pragma unroll
        for (int kk = 0; kk < 16; kk++) {
            float4 av0 = *(const float4*)&As[kk][rm];
            float4 av1 = *(const float4*)&As[kk][rm + 4];
            float4 bv0 = *(const float4*)&Bs[kk][rn];
            float4 bv1 = *(const float4*)&Bs[kk][rn + 4];
            float a[8] = {av0.x,av0.y,av0.z,av0.w,av1.x,av1.y,av1.z,av1.w};
            float b[8] = {bv0.x,bv0.y,bv0.z,bv0.w,bv1.x,bv1.y,bv1.z,bv1.w};
            #pragma unroll
            for (int i = 0; i < 8; i++)
                #pragma unroll
                for (int j = 0; j < 8; j++)
                    acc[i][j] = fmaf(a[i], b[j], acc[i][j]);
        }
    }
    #pragma unroll
    for (int i = 0; i < 8; i++) {
        int row = bm + rm + i;
        if (row >= M) continue;
        float* Cp = C + (size_t)row * Nc + bn + rn;
        #pragma unroll
        for (int j = 0; j < 8; j++) Cp[j] = acc[i][j] + bias[bn + rn + j];
    }
}

// ===================== elementwise kernels (vectorized) ======================
__global__ void make_pairs_kernel(int* __restrict__ iu, int* __restrict__ ju) {
    int p = blockIdx.x * blockDim.x + threadIdx.x;
    if (p >= PP) return;
    int off = 0;
    for (int i = 0; i < NN - 1; i++) {
        int cnt = NN - 1 - i;
        if (p < off + cnt) { iu[p] = i; ju[p] = i + 1 + (p - off); return; }
        off += cnt;
    }
}

// weights: fp32 -> fp16, 4 elts/thread
__global__ void wsplit_kernel(const float4* __restrict__ x, uint2* __restrict__ h, size_t n4) {
    size_t i = (size_t)blockIdx.x * blockDim.x + threadIdx.x;
    if (i >= n4) return;
    float4 v = x[i];
    h[i] = pack4h(v.x, v.y, v.z, v.w);
}

// activations: fp32 -> (hi, lo) fp16, 4 elts/thread; zero-fills [n4, npad4)
__global__ void asplit_kernel(const float4* __restrict__ x,
                              uint2* __restrict__ hi, uint2* __restrict__ lo,
                              size_t n4, size_t npad4)
{
    size_t i = (size_t)blockIdx.x * blockDim.x + threadIdx.x;
    if (i >= npad4) return;
    float4 v = (i < n4) ? x[i] : make_float4(0.f, 0.f, 0.f, 0.f);
    uint2 h = pack4h(v.x, v.y, v.z, v.w);
    hi[i] = h;
    __half2 h01 = *(__half2*)&h.x, h23 = *(__half2*)&h.y;
    lo[i] = pack4h(v.x - __low2float(h01),  v.y - __high2float(h01),
                   v.z - __low2float(h23),  v.w - __high2float(h23));
}

__device__ __forceinline__ float sigmoidf_(float x) { return 1.f / (1.f + expf(-x)); }
__device__ __forceinline__ float gru1(float ir, float iz, float in_, float hr, float hz,
                                      float hn, float h) {
    float r  = sigmoidf_(ir + hr);
    float z  = sigmoidf_(iz + hz);
    float nv = tanhf(in_ + r * hn);
    return (1.f - z) * nv + z * h;
}

// GRU combine + fp16 hi/lo split, 4 elts/thread. WRITE_H: also store fp32 h.
template<int WRITE_H>
__global__ void gru_combine_split(const float4* __restrict__ gh, const float4* __restrict__ gi,
                                  const int* __restrict__ node_idx, const float4* __restrict__ hprev,
                                  float4* __restrict__ hout,
                                  uint2* __restrict__ ahi, uint2* __restrict__ alo)
{
    size_t v = (size_t)blockIdx.x * blockDim.x + threadIdx.x;
    if (v >= (size_t)MPAD * (HH / 4)) return;
    if (v >= (size_t)PP * (HH / 4)) {
        uint2 z = make_uint2(0u, 0u);
        ahi[v] = z; alo[v] = z;
        return;
    }
    const int p  = (int)(v >> 9);          // / (HH/4)
    const int jv = (int)(v & 511);
    const int q  = node_idx[p];
    const float4* gip = gi + (size_t)q * (G3 / 4);
    const float4* ghp = gh + (size_t)p * (G3 / 4);
    float4 ir = gip[jv], iz = gip[jv + HH/4], in_ = gip[jv + 2*(HH/4)];
    float4 hr = ghp[jv], hz = ghp[jv + HH/4], hn  = ghp[jv + 2*(HH/4)];
    float4 hp = hprev[v];
    float4 o;
    o.x = gru1(ir.x, iz.x, in_.x, hr.x, hz.x, hn.x, hp.x);
    o.y = gru1(ir.y, iz.y, in_.y, hr.y, hz.y, hn.y, hp.y);
    o.z = gru1(ir.z, iz.z, in_.z, hr.z, hz.z, hn.z, hp.z);
    o.w = gru1(ir.w, iz.w, in_.w, hr.w, hz.w, hn.w, hp.w);
    if (WRITE_H) hout[v] = o;
    uint2 h = pack4h(o.x, o.y, o.z, o.w);
    ahi[v] = h;
    __half2 h01 = *(__half2*)&h.x, h23 = *(__half2*)&h.y;
    alo[v] = pack4h(o.x - __low2float(h01),  o.y - __high2float(h01),
                    o.z - __low2float(h23),  o.w - __high2float(h23));
}

__global__ void ln_reduce1(const float4* __restrict__ x, size_t n4, double* __restrict__ part) {
    double s = 0.0, ss = 0.0;
    size_t stride = (size_t)gridDim.x * blockDim.x;
    for (size_t i = (size_t)blockIdx.x * blockDim.x + threadIdx.x; i < n4; i += stride) {
        float4 v = x[i];
        s  += (double)v.x + (double)v.y + (double)v.z + (double)v.w;
        ss += (double)v.x * v.x + (double)v.y * v.y + (double)v.z * v.z + (double)v.w * v.w;
    }
    __shared__ double sh[256], sh2[256];
    sh[threadIdx.x] = s; sh2[threadIdx.x] = ss;
    __syncthreads();
    for (int o = 128; o > 0; o >>= 1) {
        if (threadIdx.x < o) { sh[threadIdx.x] += sh[threadIdx.x+o]; sh2[threadIdx.x] += sh2[threadIdx.x+o]; }
        __syncthreads();
    }
    if (threadIdx.x == 0) { part[blockIdx.x] = sh[0]; part[RED_BLOCKS + blockIdx.x] = sh2[0]; }
}

__global__ void ln_reduce2(const double* __restrict__ part, unsigned long long n,
                           float* __restrict__ stats) {
    __shared__ double sh[256], sh2[256];
    double s = 0.0, ss = 0.0;
    for (int i = threadIdx.x; i < RED_BLOCKS; i += 256) { s += part[i]; ss += part[RED_BLOCKS + i]; }
    sh[threadIdx.x] = s; sh2[threadIdx.x] = ss;
    __syncthreads();
    for (int o = 128; o > 0; o >>= 1) {
        if (threadIdx.x < o) { sh[threadIdx.x] += sh[threadIdx.x+o]; sh2[threadIdx.x] += sh2[threadIdx.x+o]; }
        __syncthreads();
    }
    if (threadIdx.x == 0) {
        double inv = 1.0 / (double)n;
        double mu = sh[0] * inv;
        double var = sh2[0] * inv - mu * mu;
        stats[0] = (float)mu;
        stats[1] = (float)(1.0 / sqrt(var + (double)LN_EPS));
    }
}

// LN apply -> fp16 hi/lo, 4 elts/thread
__global__ void ln_apply_split(const float4* __restrict__ x, const float4* __restrict__ w,
                               const float4* __restrict__ b, const float* __restrict__ stats,
                               uint2* __restrict__ hi, uint2* __restrict__ lo,
                               size_t n4, size_t npad4)
{
    size_t i = (size_t)blockIdx.x * blockDim.x + threadIdx.x;
    if (i >= npad4) return;
    float4 o = make_float4(0.f, 0.f, 0.f, 0.f);
    if (i < n4) {
        const float mu = stats[0], rs = stats[1];
        float4 xv = x[i], wv = w[i], bv = b[i];
        o.x = (xv.x - mu) * rs * wv.x + bv.x;
        o.y = (xv.y - mu) * rs * wv.y + bv.y;
        o.z = (xv.z - mu) * rs * wv.z + bv.z;
        o.w = (xv.w - mu) * rs * wv.w + bv.w;
    }
    uint2 h = pack4h(o.x, o.y, o.z, o.w);
    hi[i] = h;
    __half2 h01 = *(__half2*)&h.x, h23 = *(__half2*)&h.y;
    lo[i] = pack4h(o.x - __low2float(h01),  o.y - __high2float(h01),
                   o.z - __low2float(h23),  o.w - __high2float(h23));
}

// fused LN3 + final dot + sigmoid: one warp per row
__global__ void final_dot_ln_kernel(const float* __restrict__ c, const float* __restrict__ lnw,
                                    const float* __restrict__ lnb, const float* __restrict__ stats,
                                    const float* __restrict__ W4, const float* __restrict__ b4,
                                    float* __restrict__ vals)
{
    int p = blockIdx.x * 8 + (threadIdx.x >> 5);
    int lane = threadIdx.x & 31;
    if (p >= PP) return;
    const float mu = stats[0], rs = stats[1];
    const float4* cp = (const float4*)(c   + (size_t)p * H2);
    const float4* wp = (const float4*)(lnw + (size_t)p * H2);
    const float4* bp = (const float4*)(lnb + (size_t)p * H2);
    const float4* w4 = (const float4*)W4;
    float s = 0.f;
    #pragma unroll
    for (int i = lane; i < H2 / 4; i += 32) {
        float4 cv = cp[i], wv = wp[i], bv = bp[i], qv = w4[i];
        s += ((cv.x - mu) * rs * wv.x + bv.x) * qv.x
           + ((cv.y - mu) * rs * wv.y + bv.y) * qv.y
           + ((cv.z - mu) * rs * wv.z + bv.z) * qv.z
           + ((cv.w - mu) * rs * wv.w + bv.w) * qv.w;
    }
    #pragma unroll
    for (int o = 16; o > 0; o >>= 1) s += __shfl_xor_sync(0xffffffffu, s, o);
    if (lane == 0) vals[p] = 1.f / (1.f + expf(-(s + b4[0])));
}

// direct symmetric output assembly (no zero pass, no index tables)
__global__ void assemble_out_kernel(const float* __restrict__ vals, float* __restrict__ out) {
    int idx = blockIdx.x * blockDim.x + threadIdx.x;
    if (idx >= NN * NN) return;
    int i = idx / NN, j = idx % NN;
    if (i == j) { out[idx] = 0.f; return; }
    int a = min(i, j), b = max(i, j);
    int p = a * (2 * NN - a - 1) / 2 + (b - a - 1);
    out[idx] = vals[p];
}

// ===================== driver ================================================
extern "C" void kernel_launch(void* const* d_in, const int* in_sizes, int n_in,
                              void* d_out, int out_size)
{
    const float* x    = (const float*)d_in[0];
    const float* hid  = (const float*)d_in[1];
    const float* Wih  = (const float*)d_in[2];
    const float* Whh  = (const float*)d_in[3];
    const float* bih  = (const float*)d_in[4];
    const float* bhh  = (const float*)d_in[5];
    const float* W1   = (const float*)d_in[6];
    const float* b1   = (const float*)d_in[7];
    const float* ln1w = (const float*)d_in[8];
    const float* ln1b = (const float*)d_in[9];
    const float* W2   = (const float*)d_in[10];
    const float* b2   = (const float*)d_in[11];
    const float* ln2w = (const float*)d_in[12];
    const float* ln2b = (const float*)d_in[13];
    const float* W3   = (const float*)d_in[14];
    const float* b3   = (const float*)d_in[15];
    const float* ln3w = (const float*)d_in[16];
    const float* ln3b = (const float*)d_in[17];
    const float* W4   = (const float*)d_in[18];
    const float* b4   = (const float*)d_in[19];
    float* out = (float*)d_out;

    float *gi, *gh, *h1, *a, *c, *vals, *stats;
    __half *ahi, *alo, *whh, *w1, *w2, *w3;
    int *iu, *ju;
    double* part;
    cudaGetSymbolAddress((void**)&gi,    g_gi);
    cudaGetSymbolAddress((void**)&gh,    g_gh);
    cudaGetSymbolAddress((void**)&h1,    g_h1);
    cudaGetSymbolAddress((void**)&a,     g_a);
    cudaGetSymbolAddress((void**)&c,     g_c);
    cudaGetSymbolAddress((void**)&ahi,   g_ahi);
    cudaGetSymbolAddress((void**)&alo,   g_alo);
    cudaGetSymbolAddress((void**)&whh,   g_whh);
    cudaGetSymbolAddress((void**)&w1,    g_w1);
    cudaGetSymbolAddress((void**)&w2,    g_w2);
    cudaGetSymbolAddress((void**)&w3,    g_w3);
    cudaGetSymbolAddress((void**)&vals,  g_vals);
    cudaGetSymbolAddress((void**)&iu,    g_iu);
    cudaGetSymbolAddress((void**)&ju,    g_ju);
    cudaGetSymbolAddress((void**)&part,  g_part);
    cudaGetSymbolAddress((void**)&stats, g_stats);

    cudaFuncSetAttribute(mma_gemm<0>, cudaFuncAttributeMaxDynamicSharedMemorySize, GEMM_SMEM);
    cudaFuncSetAttribute(mma_gemm<1>, cudaFuncAttributeMaxDynamicSharedMemorySize, GEMM_SMEM);

    const size_t nPH4   = (size_t)PP * HH / 4;
    const size_t nPH24  = (size_t)PP * H2 / 4;
    const size_t padH4  = (size_t)MPAD * HH / 4;
    const size_t padH24 = (size_t)MPAD * H2 / 4;

    make_pairs_kernel<<<(PP + 255) / 256, 256>>>(iu, ju);

    // weight fp16 conversion (vectorized)
    wsplit_kernel<<<(unsigned)(((size_t)G3*HH/4 + 255) / 256), 256>>>((const float4*)Whh, (uint2*)whh, (size_t)G3*HH/4);
    wsplit_kernel<<<(unsigned)(((size_t)HH*HH/4 + 255) / 256), 256>>>((const float4*)W1,  (uint2*)w1,  (size_t)HH*HH/4);
    wsplit_kernel<<<(unsigned)(((size_t)H2*HH/4 + 255) / 256), 256>>>((const float4*)W2,  (uint2*)w2,  (size_t)H2*HH/4);
    wsplit_kernel<<<(unsigned)(((size_t)H2*H2/4 + 255) / 256), 256>>>((const float4*)W3,  (uint2*)w3,  (size_t)H2*H2/4);

    // gi = x @ Wih^T + bih
    {
        dim3 grid(G3 / 128, 1);
        sgemm_nt<<<grid, 256>>>(x, Wih, bih, gi, NN, G3, 64);
    }

    // GRU step 1
    asplit_kernel<<<(unsigned)((padH4 + 255) / 256), 256>>>((const float4*)hid, (uint2*)ahi, (uint2*)alo, nPH4, padH4);
    {
        dim3 grid(G3 / 128, MPAD / 128);
        mma_gemm<0><<<grid, 256, GEMM_SMEM>>>(ahi, alo, whh, bhh, gh, G3, HH);
    }
    gru_combine_split<1><<<(unsigned)((padH4 + 255) / 256), 256>>>(
        (const float4*)gh, (const float4*)gi, iu, (const float4*)hid, (float4*)h1, (uint2*)ahi, (uint2*)alo);

    // GRU step 2 (fp32 h never consumed again -> skip the write)
    {
        dim3 grid(G3 / 128, MPAD / 128);
        mma_gemm<0><<<grid, 256, GEMM_SMEM>>>(ahi, alo, whh, bhh, gh, G3, HH);
    }
    gru_combine_split<0><<<(unsigned)((padH4 + 255) / 256), 256>>>(
        (const float4*)gh, (const float4*)gi, ju, (const float4*)h1, nullptr, (uint2*)ahi, (uint2*)alo);

    // L1 + ReLU -> full LN -> split
    {
        dim3 grid(HH / 128, MPAD / 128);
        mma_gemm<1><<<grid, 256, GEMM_SMEM>>>(ahi, alo, w1, b1, a, HH, HH);
    }
    ln_reduce1<<<RED_BLOCKS, 256>>>((const float4*)a, nPH4, part);
    ln_reduce2<<<1, 256>>>(part, (unsigned long long)((size_t)PP * HH), stats);
    ln_apply_split<<<(unsigned)((padH4 + 255) / 256), 256>>>(
        (const float4*)a, (const float4*)ln1w, (const float4*)ln1b, stats, (uint2*)ahi, (uint2*)alo, nPH4, padH4);

    // L2 + ReLU -> full LN -> split
    {
        dim3 grid(H2 / 128, MPAD / 128);
        mma_gemm<1><<<grid, 256, GEMM_SMEM>>>(ahi, alo, w2, b2, c, H2, HH);
    }
    ln_reduce1<<<RED_BLOCKS, 256>>>((const float4*)c, nPH24, part);
    ln_reduce2<<<1, 256>>>(part, (unsigned long long)((size_t)PP * H2), stats);
    ln_apply_split<<<(unsigned)((padH24 + 255) / 256), 256>>>(
        (const float4*)c, (const float4*)ln2w, (const float4*)ln2b, stats, (uint2*)ahi, (uint2*)alo, nPH24, padH24);

    // L3 + ReLU -> full LN fused into final dot
    {
        dim3 grid(H2 / 128, MPAD / 128);
        mma_gemm<1><<<grid, 256, GEMM_SMEM>>>(ahi, alo, w3, b3, c, H2, H2);
    }
    ln_reduce1<<<RED_BLOCKS, 256>>>((const float4*)c, nPH24, part);
    ln_reduce2<<<1, 256>>>(part, (unsigned long long)((size_t)PP * H2), stats);
    final_dot_ln_kernel<<<(PP + 7) / 8, 256>>>(c, ln3w, ln3b, stats, W4, b4, vals);

    // direct symmetric assembly
    assemble_out_kernel<<<(NN * NN + 255) / 256, 256>>>(vals, out);
}

// round 16
// speedup vs baseline: 5.2100x; 1.4027x over previous
#include <cuda_runtime.h>
#include <cuda_fp16.h>
#include <cstdint>
#include <math.h>

#define NN   84
#define PP   3486
#define MPAD 3584           // 28 * 128
#define HH   2048
#define H2   1024
#define G3   (3*HH)         // 6144
#define LN_EPS 1e-5f
#define MAXCTA 512

// ===================== scratch (device globals) ==============================
__device__ float g_gi[(size_t)NN * G3];
__device__ float g_gh[(size_t)MPAD * G3];
__device__ float g_h1[(size_t)PP * HH];
__device__ float g_a [(size_t)MPAD * HH];
__device__ float g_c [(size_t)MPAD * H2];
__device__ __half g_ahi[(size_t)MPAD * HH];
__device__ __half g_alo[(size_t)MPAD * HH];
__device__ __half g_whh[(size_t)G3 * HH];
__device__ __half g_w1 [(size_t)HH * HH];
__device__ __half g_w2 [(size_t)H2 * HH];
__device__ __half g_w3 [(size_t)H2 * H2];
__device__ float  g_vals[PP];
__device__ int    g_iu[PP];
__device__ int    g_ju[PP];
__device__ double g_part[2 * MAXCTA];
__device__ float  g_stats[2];

// ===================== baseline PTX helpers ==================================
__device__ __forceinline__ uint32_t smem_u32(const void* p) {
    uint32_t a;
    asm("{ .reg .u64 t; cvta.to.shared.u64 t, %1; cvt.u32.u64 %0, t; }" : "=r"(a) : "l"(p));
    return a;
}
__device__ __forceinline__ void cp16(uint32_t dst, const void* src) {
    asm volatile("cp.async.cg.shared.global [%0], [%1], 16;" :: "r"(dst), "l"(src));
}
__device__ __forceinline__ void cp_commit() {
    asm volatile("cp.async.commit_group;" ::: "memory");
}
__device__ __forceinline__ void cp_wait1() {
    asm volatile("cp.async.wait_group 1;" ::: "memory");
}
__device__ __forceinline__ void ldsm4(uint32_t* r, uint32_t addr) {
    asm volatile("ldmatrix.sync.aligned.m8n8.x4.shared.b16 {%0,%1,%2,%3}, [%4];"
                 : "=r"(r[0]), "=r"(r[1]), "=r"(r[2]), "=r"(r[3]) : "r"(addr));
}
__device__ __forceinline__ void mma_f16(float* d, const uint32_t* a, uint32_t b0, uint32_t b1) {
    asm volatile("mma.sync.aligned.m16n8k16.row.col.f32.f16.f16.f32 "
                 "{%0,%1,%2,%3}, {%4,%5,%6,%7}, {%8,%9}, {%0,%1,%2,%3};"
                 : "+f"(d[0]), "+f"(d[1]), "+f"(d[2]), "+f"(d[3])
                 : "r"(a[0]), "r"(a[1]), "r"(a[2]), "r"(a[3]), "r"(b0), "r"(b1));
}
__device__ __forceinline__ uint2 pack4h(float a, float b, float c, float d) {
    __half2 lo = __floats2half2_rn(a, b);
    __half2 hi = __floats2half2_rn(c, d);
    uint2 r;
    r.x = *(uint32_t*)&lo;
    r.y = *(uint32_t*)&hi;
    return r;
}

// ===================== fp16 tensor-core GEMM =================================
// C[MPAD,Nc] = A[MPAD,K] @ W[Nc,K]^T + bias, opt ReLU.
// TWOPASS=1: A given as hi+lo fp16, two MMA streams (error-compensated).
// TWOPASS=0: plain fp16 A, single stream (used for the GRU GEMMs).
// REDUCE=1: epilogue also accumulates per-CTA sum/sumsq of stored values for
//           rows < PP into part[cta] / part[MAXCTA+cta] (deterministic).
#define ROW_B     80
#define TILE_B    (128 * ROW_B)
#define NSTAGE    3

template<int RELU, int TWOPASS, int REDUCE>
__global__ __launch_bounds__(256, 2)
void mma_gemm(const __half* __restrict__ Ahi, const __half* __restrict__ Alo,
              const __half* __restrict__ Wh,
              const float* __restrict__ bias, float* __restrict__ C,
              double* __restrict__ part, int Nc, int K)
{
    constexpr int NTILES  = 2 + TWOPASS;
    constexpr int STAGE_B = NTILES * TILE_B;
    constexpr int NL      = 2 * NTILES;

    extern __shared__ char sm[];
    const uint32_t sbase = smem_u32(sm);
    const int tid  = threadIdx.x;
    const int w    = tid >> 5;
    const int lane = tid & 31;
    const int bm   = blockIdx.y * 128;
    const int bn   = blockIdx.x * 128;

    const char* lsrc[NL];
    uint32_t    ldst[NL];
    #pragma unroll
    for (int i = 0; i < NL; i++) {
        const int o    = tid + i * 256;
        const int tile = o >> 9;              // 0..NTILES-1
        const int r    = (o >> 2) & 127;
        const int cq   = o & 3;
        const __half* base;
        int gr;
        if (tile == 0)                    { base = Ahi; gr = bm; }
        else if (TWOPASS && tile == 1)    { base = Alo; gr = bm; }
        else                              { base = Wh;  gr = bn; }
        lsrc[i] = (const char*)(base + (size_t)(gr + r) * K) + cq * 16;
        ldst[i] = sbase + tile * TILE_B + r * ROW_B + cq * 16;
    }

    const int KC = K >> 5;
    const int wm = w >> 1;
    const int wn = w & 1;

    float acc[2][8][4];
    #pragma unroll
    for (int m = 0; m < 2; m++)
        #pragma unroll
        for (int n = 0; n < 8; n++)
            #pragma unroll
            for (int q = 0; q < 4; q++) acc[m][n][q] = 0.f;

    const uint32_t a_off0 = (uint32_t)(wm * 32 + (lane & 15)) * ROW_B + ((lane >> 4) << 4);
    const uint32_t b_row  = (uint32_t)(wn * 64 + ((lane >> 4) << 3) + (lane & 7));
    const uint32_t b_off0 = b_row * ROW_B + (((lane >> 3) & 1) << 4);

    #pragma unroll
    for (int pc = 0; pc < 2; pc++) {
        const uint32_t so = pc * STAGE_B;
        const int kb = pc * 64;
        #pragma unroll
        for (int i = 0; i < NL; i++) cp16(ldst[i] + so, lsrc[i] + kb);
        cp_commit();
    }

    for (int c = 0; c < KC; c++) {
        cp_wait1();
        __syncthreads();

        if (c + 2 < KC) {
            const uint32_t so = ((c + 2) % NSTAGE) * STAGE_B;
            const int kb = (c + 2) * 64;
            #pragma unroll
            for (int i = 0; i < NL; i++) cp16(ldst[i] + so, lsrc[i] + kb);
        }
        cp_commit();

        const uint32_t st = sbase + (c % NSTAGE) * STAGE_B;
        const uint32_t Ah = st;
        const uint32_t Al = st + TILE_B;                    // valid iff TWOPASS
        const uint32_t Bh = st + (NTILES - 1) * TILE_B;

        #pragma unroll
        for (int kk = 0; kk < 2; kk++) {
            uint32_t ah[2][4], al[2][4];
            #pragma unroll
            for (int m = 0; m < 2; m++) {
                uint32_t off = a_off0 + (uint32_t)(m * 16) * ROW_B + kk * 32;
                ldsm4(ah[m], Ah + off);
                if (TWOPASS) ldsm4(al[m], Al + off);
            }
            #pragma unroll
            for (int np = 0; np < 4; np++) {
                uint32_t off = b_off0 + (uint32_t)(np * 16) * ROW_B + kk * 32;
                uint32_t bh[4];
                ldsm4(bh, Bh + off);
                #pragma unroll
                for (int t = 0; t < 2; t++) {
                    const int n = np * 2 + t;
                    #pragma unroll
                    for (int m = 0; m < 2; m++) {
                        mma_f16(acc[m][n], ah[m], bh[t*2], bh[t*2+1]);
                        if (TWOPASS) mma_f16(acc[m][n], al[m], bh[t*2], bh[t*2+1]);
                    }
                }
            }
        }
    }

    double rs = 0.0, rss = 0.0;
    #pragma unroll
    for (int m = 0; m < 2; m++) {
        const int row = bm + wm * 32 + m * 16 + (lane >> 2);
        #pragma unroll
        for (int n = 0; n < 8; n++) {
            const int col = bn + wn * 64 + n * 8 + ((lane & 3) << 1);
            const float bx = bias[col], by = bias[col + 1];
            float2 v0, v1;
            v0.x = acc[m][n][0] + bx; v0.y = acc[m][n][1] + by;
            v1.x = acc[m][n][2] + bx; v1.y = acc[m][n][3] + by;
            if (RELU) {
                v0.x = fmaxf(v0.x, 0.f); v0.y = fmaxf(v0.y, 0.f);
                v1.x = fmaxf(v1.x, 0.f); v1.y = fmaxf(v1.y, 0.f);
            }
            *(float2*)(C + (size_t)row * Nc + col)       = v0;
            *(float2*)(C + (size_t)(row + 8) * Nc + col) = v1;
            if (REDUCE) {
                if (row < PP) {
                    rs  += (double)v0.x + (double)v0.y;
                    rss += (double)v0.x * v0.x + (double)v0.y * v0.y;
                }
                if (row + 8 < PP) {
                    rs  += (double)v1.x + (double)v1.y;
                    rss += (double)v1.x * v1.x + (double)v1.y * v1.y;
                }
            }
        }
    }

    if (REDUCE) {
        __shared__ double reds[8], redss[8];
        #pragma unroll
        for (int o = 16; o > 0; o >>= 1) {
            rs  += __shfl_xor_sync(0xffffffffu, rs,  o);
            rss += __shfl_xor_sync(0xffffffffu, rss, o);
        }
        if (lane == 0) { reds[w] = rs; redss[w] = rss; }
        __syncthreads();
        if (tid == 0) {
            double s = 0.0, ss = 0.0;
            #pragma unroll
            for (int i = 0; i < 8; i++) { s += reds[i]; ss += redss[i]; }
            const int cta = blockIdx.y * gridDim.x + blockIdx.x;
            part[cta]          = s;
            part[MAXCTA + cta] = ss;
        }
    }
}

// ===================== small fp32 SGEMM (gi only) ============================
__global__ __launch_bounds__(256, 2)
void sgemm_nt(const float* __restrict__ A, const float* __restrict__ W,
              const float* __restrict__ bias, float* __restrict__ C,
              int M, int Nc, int K)
{
    __shared__ float As[16][128];
    __shared__ float Bs[16][128];
    const int tid = threadIdx.x;
    const int bm = blockIdx.y * 128, bn = blockIdx.x * 128;
    const int lrow = tid >> 1, lk = (tid & 1) << 3;
    const int rm = (tid >> 4) << 3, rn = (tid & 15) << 3;
    float acc[8][8];
    #pragma unroll
    for (int i = 0; i < 8; i++)
        #pragma unroll
        for (int j = 0; j < 8; j++) acc[i][j] = 0.f;
    const bool arow_ok = (bm + lrow) < M;
    const float* Ap = A + (size_t)(bm + lrow) * K + lk;
    const float* Wp = W + (size_t)(bn + lrow) * K + lk;
    for (int k0 = 0; k0 < K; k0 += 16) {
        float4 a0 = make_float4(0.f, 0.f, 0.f, 0.f), a1 = a0;
        if (arow_ok) { a0 = *(const float4*)(Ap + k0); a1 = *(const float4*)(Ap + k0 + 4); }
        float4 b0 = *(const float4*)(Wp + k0);
        float4 b1 = *(const float4*)(Wp + k0 + 4);
        __syncthreads();
        As[lk+0][lrow]=a0.x; As[lk+1][lrow]=a0.y; As[lk+2][lrow]=a0.z; As[lk+3][lrow]=a0.w;
        As[lk+4][lrow]=a1.x; As[lk+5][lrow]=a1.y; As[lk+6][lrow]=a1.z; As[lk+7][lrow]=a1.w;
        Bs[lk+0][lrow]=b0.x; Bs[lk+1][lrow]=b0.y; Bs[lk+2][lrow]=b0.z; Bs[lk+3][lrow]=b0.w;
        Bs[lk+4][lrow]=b1.x; Bs[lk+5][lrow]=b1.y; Bs[lk+6][lrow]=b1.z; Bs[lk+7][lrow]=b1.w;
        __syncthreads();
        #pragma unroll
        for (int kk = 0; kk < 16; kk++) {
            float4 av0 = *(const float4*)&As[kk][rm];
            float4 av1 = *(const float4*)&As[kk][rm + 4];
            float4 bv0 = *(const float4*)&Bs[kk][rn];
            float4 bv1 = *(const float4*)&Bs[kk][rn + 4];
            float a[8] = {av0.x,av0.y,av0.z,av0.w,av1.x,av1.y,av1.z,av1.w};
            float b[8] = {bv0.x,bv0.y,bv0.z,bv0.w,bv1.x,bv1.y,bv1.z,bv1.w};
            #pragma unroll
            for (int i = 0; i < 8; i++)
                #pragma unroll
                for (int j = 0; j < 8; j++)
                    acc[i][j] = fmaf(a[i], b[j], acc[i][j]);
        }
    }
    #pragma unroll
    for (int i = 0; i < 8; i++) {
        int row = bm + rm + i;
        if (row >= M) continue;
        float* Cp = C + (size_t)row * Nc + bn + rn;
        #pragma unroll
        for (int j = 0; j < 8; j++) Cp[j] = acc[i][j] + bias[bn + rn + j];
    }
}

// ===================== elementwise kernels ===================================
__global__ void make_pairs_kernel(int* __restrict__ iu, int* __restrict__ ju) {
    int p = blockIdx.x * blockDim.x + threadIdx.x;
    if (p >= PP) return;
    int off = 0;
    for (int i = 0; i < NN - 1; i++) {
        int cnt = NN - 1 - i;
        if (p < off + cnt) { iu[p] = i; ju[p] = i + 1 + (p - off); return; }
        off += cnt;
    }
}

__global__ void wsplit_kernel(const float4* __restrict__ x, uint2* __restrict__ h, size_t n4) {
    size_t i = (size_t)blockIdx.x * blockDim.x + threadIdx.x;
    if (i >= n4) return;
    float4 v = x[i];
    h[i] = pack4h(v.x, v.y, v.z, v.w);
}

// activations -> fp16 hi only (GRU GEMM is single-pass)
__global__ void asplit_hi_kernel(const float4* __restrict__ x, uint2* __restrict__ hi,
                                 size_t n4, size_t npad4)
{
    size_t i = (size_t)blockIdx.x * blockDim.x + threadIdx.x;
    if (i >= npad4) return;
    float4 v = (i < n4) ? x[i] : make_float4(0.f, 0.f, 0.f, 0.f);
    hi[i] = pack4h(v.x, v.y, v.z, v.w);
}

__device__ __forceinline__ float sigmoidf_(float x) { return 1.f / (1.f + expf(-x)); }
__device__ __forceinline__ float gru1(float ir, float iz, float in_, float hr, float hz,
                                      float hn, float h) {
    float r  = sigmoidf_(ir + hr);
    float z  = sigmoidf_(iz + hz);
    float nv = tanhf(in_ + r * hn);
    return (1.f - z) * nv + z * h;
}

// GRU combine + fp16 split, 4 elts/thread.
template<int WRITE_H, int WRITE_LO>
__global__ void gru_combine_split(const float4* __restrict__ gh, const float4* __restrict__ gi,
                                  const int* __restrict__ node_idx, const float4* __restrict__ hprev,
                                  float4* __restrict__ hout,
                                  uint2* __restrict__ ahi, uint2* __restrict__ alo)
{
    size_t v = (size_t)blockIdx.x * blockDim.x + threadIdx.x;
    if (v >= (size_t)MPAD * (HH / 4)) return;
    if (v >= (size_t)PP * (HH / 4)) {
        uint2 z = make_uint2(0u, 0u);
        ahi[v] = z;
        if (WRITE_LO) alo[v] = z;
        return;
    }
    const int p  = (int)(v >> 9);
    const int jv = (int)(v & 511);
    const int q  = node_idx[p];
    const float4* gip = gi + (size_t)q * (G3 / 4);
    const float4* ghp = gh + (size_t)p * (G3 / 4);
    float4 ir = gip[jv], iz = gip[jv + HH/4], in_ = gip[jv + 2*(HH/4)];
    float4 hr = ghp[jv], hz = ghp[jv + HH/4], hn  = ghp[jv + 2*(HH/4)];
    float4 hp = hprev[v];
    float4 o;
    o.x = gru1(ir.x, iz.x, in_.x, hr.x, hz.x, hn.x, hp.x);
    o.y = gru1(ir.y, iz.y, in_.y, hr.y, hz.y, hn.y, hp.y);
    o.z = gru1(ir.z, iz.z, in_.z, hr.z, hz.z, hn.z, hp.z);
    o.w = gru1(ir.w, iz.w, in_.w, hr.w, hz.w, hn.w, hp.w);
    if (WRITE_H) hout[v] = o;
    uint2 h = pack4h(o.x, o.y, o.z, o.w);
    ahi[v] = h;
    if (WRITE_LO) {
        __half2 h01 = *(__half2*)&h.x, h23 = *(__half2*)&h.y;
        alo[v] = pack4h(o.x - __low2float(h01),  o.y - __high2float(h01),
                        o.z - __low2float(h23),  o.w - __high2float(h23));
    }
}

// sum per-CTA GEMM partials -> stats (deterministic fixed-order tree)
__global__ void ln_reduce2_cta(const double* __restrict__ part, int ncta,
                               unsigned long long n, float* __restrict__ stats) {
    __shared__ double sh[256], sh2[256];
    double s = 0.0, ss = 0.0;
    for (int i = threadIdx.x; i < ncta; i += 256) { s += part[i]; ss += part[MAXCTA + i]; }
    sh[threadIdx.x] = s; sh2[threadIdx.x] = ss;
    __syncthreads();
    for (int o = 128; o > 0; o >>= 1) {
        if (threadIdx.x < o) { sh[threadIdx.x] += sh[threadIdx.x+o]; sh2[threadIdx.x] += sh2[threadIdx.x+o]; }
        __syncthreads();
    }
    if (threadIdx.x == 0) {
        double inv = 1.0 / (double)n;
        double mu = sh[0] * inv;
        double var = sh2[0] * inv - mu * mu;
        stats[0] = (float)mu;
        stats[1] = (float)(1.0 / sqrt(var + (double)LN_EPS));
    }
}

// LN apply -> fp16 hi/lo, 4 elts/thread
__global__ void ln_apply_split(const float4* __restrict__ x, const float4* __restrict__ w,
                               const float4* __restrict__ b, const float* __restrict__ stats,
                               uint2* __restrict__ hi, uint2* __restrict__ lo,
                               size_t n4, size_t npad4)
{
    size_t i = (size_t)blockIdx.x * blockDim.x + threadIdx.x;
    if (i >= npad4) return;
    float4 o = make_float4(0.f, 0.f, 0.f, 0.f);
    if (i < n4) {
        const float mu = stats[0], rs = stats[1];
        float4 xv = x[i], wv = w[i], bv = b[i];
        o.x = (xv.x - mu) * rs * wv.x + bv.x;
        o.y = (xv.y - mu) * rs * wv.y + bv.y;
        o.z = (xv.z - mu) * rs * wv.z + bv.z;
        o.w = (xv.w - mu) * rs * wv.w + bv.w;
    }
    uint2 h = pack4h(o.x, o.y, o.z, o.w);
    hi[i] = h;
    __half2 h01 = *(__half2*)&h.x, h23 = *(__half2*)&h.y;
    lo[i] = pack4h(o.x - __low2float(h01),  o.y - __high2float(h01),
                   o.z - __low2float(h23),  o.w - __high2float(h23));
}

// fused LN3 + final dot + sigmoid: one warp per row
__global__ void final_dot_ln_kernel(const float* __restrict__ c, const float* __restrict__ lnw,
                                    const float* __restrict__ lnb, const float* __restrict__ stats,
                                    const float* __restrict__ W4, const float* __restrict__ b4,
                                    float* __restrict__ vals)
{
    int p = blockIdx.x * 8 + (threadIdx.x >> 5);
    int lane = threadIdx.x & 31;
    if (p >= PP) return;
    const float mu = stats[0], rs = stats[1];
    const float4* cp = (const float4*)(c   + (size_t)p * H2);
    const float4* wp = (const float4*)(lnw + (size_t)p * H2);
    const float4* bp = (const float4*)(lnb + (size_t)p * H2);
    const float4* w4 = (const float4*)W4;
    float s = 0.f;
    #pragma unroll
    for (int i = lane; i < H2 / 4; i += 32) {
        float4 cv = cp[i], wv = wp[i], bv = bp[i], qv = w4[i];
        s += ((cv.x - mu) * rs * wv.x + bv.x) * qv.x
           + ((cv.y - mu) * rs * wv.y + bv.y) * qv.y
           + ((cv.z - mu) * rs * wv.z + bv.z) * qv.z
           + ((cv.w - mu) * rs * wv.w + bv.w) * qv.w;
    }
    #pragma unroll
    for (int o = 16; o > 0; o >>= 1) s += __shfl_xor_sync(0xffffffffu, s, o);
    if (lane == 0) vals[p] = 1.f / (1.f + expf(-(s + b4[0])));
}

// direct symmetric output assembly
__global__ void assemble_out_kernel(const float* __restrict__ vals, float* __restrict__ out) {
    int idx = blockIdx.x * blockDim.x + threadIdx.x;
    if (idx >= NN * NN) return;
    int i = idx / NN, j = idx % NN;
    if (i == j) { out[idx] = 0.f; return; }
    int a = min(i, j), b = max(i, j);
    int p = a * (2 * NN - a - 1) / 2 + (b - a - 1);
    out[idx] = vals[p];
}

// ===================== driver ================================================
extern "C" void kernel_launch(void* const* d_in, const int* in_sizes, int n_in,
                              void* d_out, int out_size)
{
    const float* x    = (const float*)d_in[0];
    const float* hid  = (const float*)d_in[1];
    const float* Wih  = (const float*)d_in[2];
    const float* Whh  = (const float*)d_in[3];
    const float* bih  = (const float*)d_in[4];
    const float* bhh  = (const float*)d_in[5];
    const float* W1   = (const float*)d_in[6];
    const float* b1   = (const float*)d_in[7];
    const float* ln1w = (const float*)d_in[8];
    const float* ln1b = (const float*)d_in[9];
    const float* W2   = (const float*)d_in[10];
    const float* b2   = (const float*)d_in[11];
    const float* ln2w = (const float*)d_in[12];
    const float* ln2b = (const float*)d_in[13];
    const float* W3   = (const float*)d_in[14];
    const float* b3   = (const float*)d_in[15];
    const float* ln3w = (const float*)d_in[16];
    const float* ln3b = (const float*)d_in[17];
    const float* W4   = (const float*)d_in[18];
    const float* b4   = (const float*)d_in[19];
    float* out = (float*)d_out;

    float *gi, *gh, *h1, *a, *c, *vals, *stats;
    __half *ahi, *alo, *whh, *w1, *w2, *w3;
    int *iu, *ju;
    double* part;
    cudaGetSymbolAddress((void**)&gi,    g_gi);
    cudaGetSymbolAddress((void**)&gh,    g_gh);
    cudaGetSymbolAddress((void**)&h1,    g_h1);
    cudaGetSymbolAddress((void**)&a,     g_a);
    cudaGetSymbolAddress((void**)&c,     g_c);
    cudaGetSymbolAddress((void**)&ahi,   g_ahi);
    cudaGetSymbolAddress((void**)&alo,   g_alo);
    cudaGetSymbolAddress((void**)&whh,   g_whh);
    cudaGetSymbolAddress((void**)&w1,    g_w1);
    cudaGetSymbolAddress((void**)&w2,    g_w2);
    cudaGetSymbolAddress((void**)&w3,    g_w3);
    cudaGetSymbolAddress((void**)&vals,  g_vals);
    cudaGetSymbolAddress((void**)&iu,    g_iu);
    cudaGetSymbolAddress((void**)&ju,    g_ju);
    cudaGetSymbolAddress((void**)&part,  g_part);
    cudaGetSymbolAddress((void**)&stats, g_stats);

    const int SMEM_1P = NSTAGE * 2 * TILE_B;   // 61440
    const int SMEM_2P = NSTAGE * 3 * TILE_B;   // 92160
    cudaFuncSetAttribute(mma_gemm<0,0,0>, cudaFuncAttributeMaxDynamicSharedMemorySize, SMEM_1P);
    cudaFuncSetAttribute(mma_gemm<1,1,1>, cudaFuncAttributeMaxDynamicSharedMemorySize, SMEM_2P);

    const size_t nPH4   = (size_t)PP * HH / 4;
    const size_t nPH24  = (size_t)PP * H2 / 4;
    const size_t padH4  = (size_t)MPAD * HH / 4;
    const size_t padH24 = (size_t)MPAD * H2 / 4;

    make_pairs_kernel<<<(PP + 255) / 256, 256>>>(iu, ju);

    // weight fp16 conversion
    wsplit_kernel<<<(unsigned)(((size_t)G3*HH/4 + 255) / 256), 256>>>((const float4*)Whh, (uint2*)whh, (size_t)G3*HH/4);
    wsplit_kernel<<<(unsigned)(((size_t)HH*HH/4 + 255) / 256), 256>>>((const float4*)W1,  (uint2*)w1,  (size_t)HH*HH/4);
    wsplit_kernel<<<(unsigned)(((size_t)H2*HH/4 + 255) / 256), 256>>>((const float4*)W2,  (uint2*)w2,  (size_t)H2*HH/4);
    wsplit_kernel<<<(unsigned)(((size_t)H2*H2/4 + 255) / 256), 256>>>((const float4*)W3,  (uint2*)w3,  (size_t)H2*H2/4);

    // gi = x @ Wih^T + bih
    {
        dim3 grid(G3 / 128, 1);
        sgemm_nt<<<grid, 256>>>(x, Wih, bih, gi, NN, G3, 64);
    }

    // GRU step 1 (single-pass fp16 GEMM)
    asplit_hi_kernel<<<(unsigned)((padH4 + 255) / 256), 256>>>((const float4*)hid, (uint2*)ahi, nPH4, padH4);
    {
        dim3 grid(G3 / 128, MPAD / 128);
        mma_gemm<0,0,0><<<grid, 256, SMEM_1P>>>(ahi, nullptr, whh, bhh, gh, nullptr, G3, HH);
    }
    gru_combine_split<1,0><<<(unsigned)((padH4 + 255) / 256), 256>>>(
        (const float4*)gh, (const float4*)gi, iu, (const float4*)hid, (float4*)h1, (uint2*)ahi, nullptr);

    // GRU step 2 (single-pass fp16 GEMM)
    {
        dim3 grid(G3 / 128, MPAD / 128);
        mma_gemm<0,0,0><<<grid, 256, SMEM_1P>>>(ahi, nullptr, whh, bhh, gh, nullptr, G3, HH);
    }
    gru_combine_split<0,1><<<(unsigned)((padH4 + 255) / 256), 256>>>(
        (const float4*)gh, (const float4*)gi, ju, (const float4*)h1, nullptr, (uint2*)ahi, (uint2*)alo);

    // L1 + ReLU (2-pass GEMM, fused LN reduction) -> stats -> apply
    {
        dim3 grid(HH / 128, MPAD / 128);   // 16 x 28 = 448 CTAs
        mma_gemm<1,1,1><<<grid, 256, SMEM_2P>>>(ahi, alo, w1, b1, a, part, HH, HH);
        ln_reduce2_cta<<<1, 256>>>(part, 448, (unsigned long long)((size_t)PP * HH), stats);
    }
    ln_apply_split<<<(unsigned)((padH4 + 255) / 256), 256>>>(
        (const float4*)a, (const float4*)ln1w, (const float4*)ln1b, stats, (uint2*)ahi, (uint2*)alo, nPH4, padH4);

    // L2 + ReLU -> stats -> apply
    {
        dim3 grid(H2 / 128, MPAD / 128);   // 8 x 28 = 224 CTAs
        mma_gemm<1,1,1><<<grid, 256, SMEM_2P>>>(ahi, alo, w2, b2, c, part, H2, HH);
        ln_reduce2_cta<<<1, 256>>>(part, 224, (unsigned long long)((size_t)PP * H2), stats);
    }
    ln_apply_split<<<(unsigned)((padH24 + 255) / 256), 256>>>(
        (const float4*)c, (const float4*)ln2w, (const float4*)ln2b, stats, (uint2*)ahi, (uint2*)alo, nPH24, padH24);

    // L3 + ReLU -> stats -> fused LN + dot + sigmoid
    {
        dim3 grid(H2 / 128, MPAD / 128);
        mma_gemm<1,1,1><<<grid, 256, SMEM_2P>>>(ahi, alo, w3, b3, c, part, H2, H2);
        ln_reduce2_cta<<<1, 256>>>(part, 224, (unsigned long long)((size_t)PP * H2), stats);
    }
    final_dot_ln_kernel<<<(PP + 7) / 8, 256>>>(c, ln3w, ln3b, stats, W4, b4, vals);

    // direct symmetric assembly
    assemble_out_kernel<<<(NN * NN + 255) / 256, 256>>>(vals, out);
}